// round 11
// baseline (speedup 1.0000x reference)
#include <cuda_runtime.h>

// ---------------------------------------------------------------------------
// VQ-VAE forward, fp32, Eigen-chain-order-exact encoder/VQ, f32x2-packed FMA.
// Round 10: e3 -> 3 CTAs/SM (4ow x 8oc tile, packed 76.8KB smem);
// vq -> 2-row blocks 52.4KB (3 CTAs), s_e/bv union. Rest verbatim R9.
// ---------------------------------------------------------------------------

typedef unsigned long long u64;

__device__ float g_h1[64 * 32 * 128 * 128];
__device__ float g_h2[64 * 64 * 64 * 64];
__device__ float g_d1o[64 * 32 * 64 * 64];
__device__ float g_d2o[64 * 64 * 128 * 128];
__device__ float g_en[512];
__device__ float g_embT[64 * 512];   // [c][code]

__device__ __forceinline__ u64 pk2(float x, float y) {
    u64 r; asm("mov.b64 %0, {%1, %2};" : "=l"(r) : "f"(x), "f"(y)); return r;
}
__device__ __forceinline__ u64 f2fma(u64 a, u64 b, u64 c) {
    u64 d; asm("fma.rn.f32x2 %0, %1, %2, %3;" : "=l"(d) : "l"(a), "l"(b), "l"(c)); return d;
}
__device__ __forceinline__ float2 upk(u64 v) {
    float2 f; asm("mov.b64 {%0, %1}, %2;" : "=f"(f.x), "=f"(f.y) : "l"(v)); return f;
}

// --------------- codebook norms + transpose --------------------------------
__global__ void k_en(const float* __restrict__ emb) {
    int k = blockIdx.x * blockDim.x + threadIdx.x;
    if (k < 512) {
        float s = 0.f;
        for (int c = 0; c < 64; c++) {
            float v = emb[k * 64 + c];
            s = __fadd_rn(s, __fmul_rn(v, v));
            g_embT[c * 512 + k] = v;
        }
        g_en[k] = s;
    }
}

// ------------------------- e1 (verbatim) -----------------------------------
__global__ __launch_bounds__(128) void k_e1(const float* __restrict__ x,
                                            const float* __restrict__ w,
                                            const float* __restrict__ b) {
    __shared__ float s_in[4 * 258];
    __shared__ float s_w[512];
    const int oh = blockIdx.x, n = blockIdx.y, t = threadIdx.x;
    const int lane = t & 31, wrp = t >> 5;
    {
        int r = wrp;
        int ih = 2 * oh - 1 + r;
        bool rowok = (ih >= 0 && ih < 256);
        const float* src = x + n * 65536 + ih * 256;
        float* dst = s_in + r * 258;
#pragma unroll
        for (int k = 0; k < 9; k++) {
            int c = lane + 32 * k;
            if (c < 258) {
                int iw = c - 1;
                dst[c] = (rowok && iw >= 0 && iw < 256) ? src[iw] : 0.f;
            }
        }
    }
    for (int i = t; i < 512; i += 128) s_w[i] = w[i];
    __syncthreads();
    float acc[32];
#pragma unroll
    for (int o = 0; o < 32; o++) acc[o] = 0.f;
    const int ow = t;
#pragma unroll
    for (int k = 0; k < 16; k++) {
        float v = s_in[(k >> 2) * 258 + 2 * ow + (k & 3)];
#pragma unroll
        for (int o = 0; o < 32; o++) acc[o] = fmaf(v, s_w[o * 16 + k], acc[o]);
    }
    for (int o = 0; o < 32; o++) {
        float r = __fadd_rn(acc[o], b[o]);
        g_h1[((n * 32 + o) * 128 + oh) * 128 + ow] = r > 0.f ? r : 0.f;
    }
}

// ------------------------- e2 (verbatim R9) --------------------------------
__global__ __launch_bounds__(256) void k_e2(const float* __restrict__ w,
                                            const float* __restrict__ b) {
    extern __shared__ float sm[];
    float* s_in = sm;            // 32*10*68 = 21760
    float* s_w  = sm + 21760;    // per (kh,kw): [ic32][oc64] = 2048
    const int bx = blockIdx.x, n = blockIdx.y, t = threadIdx.x;
    const int ow0 = (bx & 1) * 32, oh0 = (bx >> 1) * 4;
    const int tow = t & 7, toh = (t >> 3) & 3, tog = t >> 5;
    const int lane = t & 31, wrp = t >> 5;
#pragma unroll 1
    for (int m = 0; m < 40; m++) {
        int row = wrp * 40 + m;
        int r = row >> 5, ic = row & 31;
        int ih = 2 * oh0 - 1 + r;
        bool rowok = (ih >= 0 && ih < 128);
        const float* src = g_h1 + ((n * 32 + ic) * 128 + ih) * 128;
        float* dst = s_in + ic * 680 + r * 68;
#pragma unroll
        for (int k = 0; k < 3; k++) {
            int c = lane + 32 * k;
            if (c < 66) {
                int iw = 2 * ow0 - 1 + c;
                dst[(c & 1) * 34 + (c >> 1)] =
                    (rowok && iw >= 0 && iw < 128) ? src[iw] : 0.f;
            }
        }
    }
    u64 acc[4][4];
#pragma unroll
    for (int i = 0; i < 4; i++)
#pragma unroll
        for (int j = 0; j < 4; j++) acc[i][j] = 0ull;
#pragma unroll 1
    for (int kh = 0; kh < 4; kh++) {
#pragma unroll 1
        for (int kw = 0; kw < 4; kw++) {
            __syncthreads();
            for (int i = t; i < 2048; i += 256) {
                int ic = i >> 6, oc = i & 63;
                s_w[i] = w[((oc * 32 + ic) << 4) + (kh << 2) + kw];
            }
            __syncthreads();
            const float* pin = s_in + (2 * toh + kh) * 68
                                    + (kw & 1) * 34 + (kw >> 1) + tow;
            const float* pwb = s_w + (tog << 3);
#pragma unroll 4
            for (int ic = 0; ic < 32; ic++) {
                const float* pw = pwb + (ic << 6);
                ulonglong2 wa = *(const ulonglong2*)(pw);
                ulonglong2 wb = *(const ulonglong2*)(pw + 4);
                const float* q = pin + ic * 680;
#pragma unroll
                for (int i = 0; i < 4; i++) {
                    float v = q[8 * i];
                    u64 vv = pk2(v, v);
                    acc[i][0] = f2fma(vv, wa.x, acc[i][0]);
                    acc[i][1] = f2fma(vv, wa.y, acc[i][1]);
                    acc[i][2] = f2fma(vv, wb.x, acc[i][2]);
                    acc[i][3] = f2fma(vv, wb.y, acc[i][3]);
                }
            }
        }
    }
    const int oh = oh0 + toh;
#pragma unroll
    for (int i = 0; i < 4; i++) {
        int ow = ow0 + tow + 8 * i;
#pragma unroll
        for (int j = 0; j < 4; j++) {
            float2 f = upk(acc[i][j]);
            int oc0 = tog * 8 + 2 * j;
            float r0 = __fadd_rn(f.x, b[oc0]);
            float r1 = __fadd_rn(f.y, b[oc0 + 1]);
            g_h2[((n * 64 + oc0) * 64 + oh) * 64 + ow]     = r0 > 0.f ? r0 : 0.f;
            g_h2[((n * 64 + oc0 + 1) * 64 + oh) * 64 + ow] = r1 > 0.f ? r1 : 0.f;
        }
    }
}

// ------------------------- e3: 64->64, k3 s1 p1, relu ----------------------
// 3 CTAs/SM: block 32ow x 4oh x 64oc. Thread: 4 ow (tow+8i) x 8 oc.
// Lanes tow(8) x toh(4); rows at 40-float offsets (8r mod 32 banks),
// ic-stride 236. s_w per (kh,kw) [ic64][oc64]. Total smem 76800 B.
__global__ __launch_bounds__(256) void k_e3(const float* __restrict__ w,
                                            const float* __restrict__ b,
                                            float* __restrict__ ze) {
    extern __shared__ float sm[];
    float* s_in = sm;            // 64 * 236 = 15104 fl
    float* s_w  = sm + 15104;    // 4096 fl
    const int bx = blockIdx.x, n = blockIdx.y, t = threadIdx.x;
    const int ow0 = (bx & 1) * 32, oh0 = (bx >> 1) * 4;
    const int tow = t & 7, toh = (t >> 3) & 3, tog = t >> 5;
    const int lane = t & 31, wrp = t >> 5;
#pragma unroll 1
    for (int m = 0; m < 48; m++) {           // 384 rows = [r6][ic64]
        int row = wrp * 48 + m;
        int r = row >> 6, ic = row & 63;
        int ih = oh0 - 1 + r;
        bool rowok = (ih >= 0 && ih < 64);
        const float* src = g_h2 + ((n * 64 + ic) * 64 + ih) * 64;
        float* dst = s_in + ic * 236 + r * 40;
        {
            int c = lane;
            int iw = ow0 + c - 1;
            dst[c] = (rowok && iw >= 0 && iw < 64) ? src[iw] : 0.f;
        }
        if (lane < 2) {
            int c = 32 + lane;
            int iw = ow0 + c - 1;
            dst[c] = (rowok && iw >= 0 && iw < 64) ? src[iw] : 0.f;
        }
    }
    u64 acc[4][4];
#pragma unroll
    for (int i = 0; i < 4; i++)
#pragma unroll
        for (int j = 0; j < 4; j++) acc[i][j] = 0ull;
#pragma unroll 1
    for (int kh = 0; kh < 3; kh++) {
#pragma unroll 1
        for (int kw = 0; kw < 3; kw++) {
            __syncthreads();
            for (int i = t; i < 4096; i += 256) {
                int ic = i >> 6, oc = i & 63;
                s_w[i] = w[(oc * 64 + ic) * 9 + kh * 3 + kw];
            }
            __syncthreads();
            const float* pin = s_in + (toh + kh) * 40 + tow + kw;
            const float* pwb = s_w + (tog << 3);
#pragma unroll 4
            for (int ic = 0; ic < 64; ic++) {
                const float* pw = pwb + (ic << 6);
                ulonglong2 wa = *(const ulonglong2*)(pw);
                ulonglong2 wb = *(const ulonglong2*)(pw + 4);
                const float* q = pin + ic * 236;
#pragma unroll
                for (int i = 0; i < 4; i++) {
                    float v = q[8 * i];
                    u64 vv = pk2(v, v);
                    acc[i][0] = f2fma(vv, wa.x, acc[i][0]);
                    acc[i][1] = f2fma(vv, wa.y, acc[i][1]);
                    acc[i][2] = f2fma(vv, wb.x, acc[i][2]);
                    acc[i][3] = f2fma(vv, wb.y, acc[i][3]);
                }
            }
        }
    }
    const int oh = oh0 + toh;
#pragma unroll
    for (int i = 0; i < 4; i++) {
        int ow = ow0 + tow + 8 * i;
#pragma unroll
        for (int j = 0; j < 4; j++) {
            float2 f = upk(acc[i][j]);
            int oc0 = tog * 8 + 2 * j;
            float r0 = __fadd_rn(f.x, b[oc0]);
            float r1 = __fadd_rn(f.y, b[oc0 + 1]);
            ze[((n * 64 + oc0) * 64 + oh) * 64 + ow]     = r0 > 0.f ? r0 : 0.f;
            ze[((n * 64 + oc0 + 1) * 64 + oh) * 64 + ow] = r1 > 0.f ? r1 : 0.f;
        }
    }
}

// ------------------------- VQ argmin + gather ------------------------------
// Block: 2 h rows x 64 pos. Thread: tpos(16) x th(2) x kg(8=warp);
// 4 pos (tpos+16i) x 8 codes. s_z row stride 4112 (16*th+tpos banks).
// s_e unioned with bv/bi (used after mainloop). smem 52416 B -> 3 CTAs.
__global__ __launch_bounds__(256) void k_vq(const float* __restrict__ ze,
                                            const float* __restrict__ emb,
                                            float* __restrict__ zq) {
    extern __shared__ float sm[];
    float* s_z  = sm;            // 2 * 4112 = 8224
    float* s_e  = sm + 8224;     // 4096 (union: bv 1024 + bi 1024 after loop)
    float* s_en = sm + 12320;    // 512
    float* s_zz = sm + 12832;    // 2 * 72 = 144
    int*   s_idx = (int*)(sm + 12976);  // 128
    float* s_bv = s_e;
    int*   s_bi = (int*)(s_e + 1024);
    const int h0 = blockIdx.x * 2, n = blockIdx.y, t = threadIdx.x;
    const int tpos = t & 15, th = (t >> 4) & 1, kg = t >> 5;
    for (int i = t; i < 8192; i += 256) {
        int c = i >> 7, hh = (i >> 6) & 1, pos = i & 63;
        s_z[hh * 4112 + c * 64 + pos] =
            ze[n * 262144 + c * 4096 + (h0 + hh) * 64 + pos];
    }
    for (int i = t; i < 512; i += 256) s_en[i] = g_en[i];
    __syncthreads();
    if (t < 128) {
        int hh = t >> 6, pp = t & 63;
        float a = 0.f;
        for (int c = 0; c < 64; c++) {
            float v = s_z[hh * 4112 + c * 64 + pp];
            a = __fadd_rn(a, __fmul_rn(v, v));
        }
        s_zz[hh * 72 + pp] = a;
    }
    float bv[4];
    int bi[4];
#pragma unroll
    for (int i = 0; i < 4; i++) { bv[i] = 3.4e38f; bi[i] = 0; }
#pragma unroll 1
    for (int ch = 0; ch < 8; ch++) {
        __syncthreads();
        for (int i = t; i < 4096; i += 256)
            s_e[i] = g_embT[(i >> 6) * 512 + ch * 64 + (i & 63)];
        __syncthreads();
        u64 dot[4][4];
#pragma unroll
        for (int i = 0; i < 4; i++)
#pragma unroll
            for (int j = 0; j < 4; j++) dot[i][j] = 0ull;
        const float* pz = s_z + th * 4112 + tpos;
        const float* peb = s_e + kg * 8;
#pragma unroll 2
        for (int c = 0; c < 64; c++) {
            const float* pe = peb + (c << 6);
            ulonglong2 e01 = *(const ulonglong2*)(pe);
            ulonglong2 e23 = *(const ulonglong2*)(pe + 4);
            const float* q = pz + (c << 6);
#pragma unroll
            for (int i = 0; i < 4; i++) {
                float v = q[16 * i];
                u64 vv = pk2(v, v);
                dot[i][0] = f2fma(vv, e01.x, dot[i][0]);
                dot[i][1] = f2fma(vv, e01.y, dot[i][1]);
                dot[i][2] = f2fma(vv, e23.x, dot[i][2]);
                dot[i][3] = f2fma(vv, e23.y, dot[i][3]);
            }
        }
#pragma unroll
        for (int i = 0; i < 4; i++) {
            float zz = s_zz[th * 72 + tpos + 16 * i];
#pragma unroll
            for (int j = 0; j < 4; j++) {
                float2 f = upk(dot[i][j]);
                int code0 = ch * 64 + kg * 8 + 2 * j;
                float d0 = __fadd_rn(__fsub_rn(zz, __fmul_rn(2.0f, f.x)), s_en[code0]);
                float d1 = __fadd_rn(__fsub_rn(zz, __fmul_rn(2.0f, f.y)), s_en[code0 + 1]);
                if (d0 < bv[i]) { bv[i] = d0; bi[i] = code0; }
                if (d1 < bv[i]) { bv[i] = d1; bi[i] = code0 + 1; }
            }
        }
    }
    __syncthreads();   // all reads of s_e done before union overwrite
#pragma unroll
    for (int i = 0; i < 4; i++) {
        int pos = tpos + 16 * i;
        s_bv[(kg * 2 + th) * 64 + pos] = bv[i];
        s_bi[(kg * 2 + th) * 64 + pos] = bi[i];
    }
    __syncthreads();
    if (t < 128) {
        int hh = t >> 6, pp = t & 63;
        float bb = s_bv[hh * 64 + pp];
        int ii = s_bi[hh * 64 + pp];
        for (int q = 1; q < 8; q++) {
            float v2 = s_bv[(q * 2 + hh) * 64 + pp];
            int i2 = s_bi[(q * 2 + hh) * 64 + pp];
            if (v2 < bb || (v2 == bb && i2 < ii)) { bb = v2; ii = i2; }
        }
        s_idx[hh * 64 + pp] = ii;
    }
    __syncthreads();
    for (int i = t; i < 8192; i += 256) {
        int c = i >> 7, hh = (i >> 6) & 1, wq = i & 63;
        zq[n * 262144 + c * 4096 + (h0 + hh) * 64 + wq] =
            emb[s_idx[hh * 64 + wq] * 64 + c];
    }
}

// --------------- d1 (verbatim R9) ------------------------------------------
__global__ __launch_bounds__(256) void k_d1(const float* __restrict__ ze,
                                            const float* __restrict__ zq,
                                            const float* __restrict__ w,
                                            const float* __restrict__ b) {
    extern __shared__ float sm[];
    float* s_in = sm;            // 64*400 = 25600
    float* s_w  = sm + 25600;    // per (kh,kw): [ic64][oc32] = 2048
    const int bx = blockIdx.x, n = blockIdx.y, t = threadIdx.x;
    const int ow0 = (bx & 1) * 32, oh0 = (bx >> 1) * 8;
    const int tow = t & 7, toh = (t >> 3) & 7, tog = t >> 6;
    const int lane = t & 31, wrp = t >> 5;
#pragma unroll 1
    for (int m = 0; m < 80; m++) {
        int row = wrp * 80 + m;
        int r = row >> 6, ic = row & 63;
        int ih = oh0 - 1 + r;
        bool rowok = (ih >= 0 && ih < 64);
        const float* pz = ze + ((n * 64 + ic) * 64 + ih) * 64;
        const float* pq = zq + ((n * 64 + ic) * 64 + ih) * 64;
        float* dst = s_in + ic * 400 + r * 40;
        {
            int c = lane;
            int iw = ow0 + c - 1;
            float v = 0.f;
            if (rowok && iw >= 0 && iw < 64) {
                float a = pz[iw], q = pq[iw];
                v = __fadd_rn(a, __fsub_rn(q, a));
            }
            dst[c] = v;
        }
        if (lane < 2) {
            int c = 32 + lane;
            int iw = ow0 + c - 1;
            float v = 0.f;
            if (rowok && iw >= 0 && iw < 64) {
                float a = pz[iw], q = pq[iw];
                v = __fadd_rn(a, __fsub_rn(q, a));
            }
            dst[c] = v;
        }
    }
    u64 acc[4][4];
#pragma unroll
    for (int i = 0; i < 4; i++)
#pragma unroll
        for (int j = 0; j < 4; j++) acc[i][j] = 0ull;
#pragma unroll 1
    for (int kh = 0; kh < 3; kh++) {
#pragma unroll 1
        for (int kw = 0; kw < 3; kw++) {
            __syncthreads();
            for (int i = t; i < 2048; i += 256) {
                int ic = i >> 5, oc = i & 31;
                s_w[i] = w[(ic * 32 + oc) * 9 + 8 - kh * 3 - kw];
            }
            __syncthreads();
            const float* pin = s_in + (toh + kh) * 40 + tow + kw;
            const float* pwb = s_w + (tog << 3);
#pragma unroll 2
            for (int ic = 0; ic < 64; ic++) {
                const float* pw = pwb + (ic << 5);
                ulonglong2 wa = *(const ulonglong2*)(pw);
                ulonglong2 wb = *(const ulonglong2*)(pw + 4);
                const float* q = pin + ic * 400;
#pragma unroll
                for (int i = 0; i < 4; i++) {
                    float v = q[8 * i];
                    u64 vv = pk2(v, v);
                    acc[i][0] = f2fma(vv, wa.x, acc[i][0]);
                    acc[i][1] = f2fma(vv, wa.y, acc[i][1]);
                    acc[i][2] = f2fma(vv, wb.x, acc[i][2]);
                    acc[i][3] = f2fma(vv, wb.y, acc[i][3]);
                }
            }
        }
    }
    const int oh = oh0 + toh;
#pragma unroll
    for (int i = 0; i < 4; i++) {
        int ow = ow0 + tow + 8 * i;
#pragma unroll
        for (int j = 0; j < 4; j++) {
            float2 f = upk(acc[i][j]);
            int oc0 = tog * 8 + 2 * j;
            float r0 = f.x + b[oc0];
            float r1 = f.y + b[oc0 + 1];
            g_d1o[((n * 32 + oc0) * 64 + oh) * 64 + ow]     = r0 > 0.f ? r0 : 0.f;
            g_d1o[((n * 32 + oc0 + 1) * 64 + oh) * 64 + ow] = r1 > 0.f ? r1 : 0.f;
        }
    }
}

// --------------- d2 (verbatim R9) ------------------------------------------
__global__ __launch_bounds__(256) void k_d2(const float* __restrict__ w,
                                            const float* __restrict__ b) {
    __shared__ __align__(16) float s_in[2112];
    __shared__ __align__(16) float s_w[8192];
    const int oh = blockIdx.x, n = blockIdx.y, t = threadIdx.x;
    const int p = t & 1, u = (t >> 1) & 15, tog = t >> 5;
    const int lane = t & 31, wrp = t >> 5;
    const int kh_a = 1 - (oh & 1);
    const int ih_a = (oh + 1 - kh_a) >> 1;
    const int kw_a = 1 - p;
    u64 acc[4][4];
#pragma unroll
    for (int i = 0; i < 4; i++)
#pragma unroll
        for (int j = 0; j < 4; j++) acc[i][j] = 0ull;
#pragma unroll 1
    for (int cc = 0; cc < 2; cc++) {
        __syncthreads();
#pragma unroll
        for (int m = 0; m < 4; m++) {
            int row = wrp * 4 + m;
            int r = row >> 4, ic = row & 15;
            int ih = (r == 0) ? ih_a : ih_a - 1;
            bool rowok = (ih >= 0 && ih < 64);
            const float* src = g_d1o + ((n * 32 + cc * 16 + ic) * 64 + ih) * 64;
            float* dst = s_in + row * 66;
#pragma unroll
            for (int k = 0; k < 3; k++) {
                int c = lane + 32 * k;
                if (c < 66) {
                    int iw = c - 1;
                    dst[c] = (rowok && iw >= 0 && iw < 64) ? src[iw] : 0.f;
                }
            }
        }
        for (int i = t; i < 8192; i += 256) {
            int ic = i >> 9, rem = i & 511;
            int r = rem >> 8, kw = (rem >> 6) & 3, oc = rem & 63;
            s_w[i] = w[(((cc * 16 + ic) * 64 + oc) << 4) + (kh_a + 2 * r) * 4 + kw];
        }
        __syncthreads();
#pragma unroll 2
        for (int ic = 0; ic < 16; ic++) {
#pragma unroll
            for (int r = 0; r < 2; r++) {
#pragma unroll
                for (int m = 0; m < 2; m++) {
                    int kw = kw_a + 2 * m;
                    const ulonglong2* pw = (const ulonglong2*)(s_w + ((ic * 2 + r) * 4 + kw) * 64 + tog * 8);
                    const float* q = s_in + r * 1056 + ic * 66 + u + p - m + 1;
                    ulonglong2 w01 = pw[0], w23 = pw[1];
#pragma unroll
                    for (int i = 0; i < 4; i++) {
                        float v = q[16 * i];
                        u64 vv = pk2(v, v);
                        acc[i][0] = f2fma(vv, w01.x, acc[i][0]);
                        acc[i][1] = f2fma(vv, w01.y, acc[i][1]);
                        acc[i][2] = f2fma(vv, w23.x, acc[i][2]);
                        acc[i][3] = f2fma(vv, w23.y, acc[i][3]);
                    }
                }
            }
        }
    }
#pragma unroll
    for (int i = 0; i < 4; i++) {
        int ow = 2 * (u + 16 * i) + p;
#pragma unroll
        for (int j = 0; j < 4; j++) {
            float2 f = upk(acc[i][j]);
            int oc0 = tog * 8 + 2 * j;
            float r0 = f.x + b[oc0];
            float r1 = f.y + b[oc0 + 1];
            g_d2o[((n * 64 + oc0) * 128 + oh) * 128 + ow]     = r0 > 0.f ? r0 : 0.f;
            g_d2o[((n * 64 + oc0 + 1) * 128 + oh) * 128 + ow] = r1 > 0.f ? r1 : 0.f;
        }
    }
}

// --------------- d3 (verbatim R9) ------------------------------------------
__global__ __launch_bounds__(256) void k_d3(const float* __restrict__ w,
                                            const float* __restrict__ bb,
                                            float* __restrict__ xh) {
    __shared__ float s_in[8320];
    __shared__ float s_w[512];
    const int oh = blockIdx.x, n = blockIdx.y, t = threadIdx.x;
    const int ow = t;
    const int lane = t & 31, wrp = t >> 5;
    const int kh_a = 1 - (oh & 1);
    const int ih_a = (oh + 1 - kh_a) >> 1;
    const int ih_b = ih_a - 1;
    const int kw_a = 1 - (ow & 1);
    const int iw_a = (ow + 1 - kw_a) >> 1;
    for (int i = t; i < 512; i += 256) {
        int ic = i >> 3, r = (i >> 2) & 1, kw = i & 3;
        int kh = kh_a + 2 * r;
        s_w[i] = w[ic * 16 + kh * 4 + kw];
    }
    float acc = 0.f;
#pragma unroll 1
    for (int cc = 0; cc < 2; cc++) {
        __syncthreads();
#pragma unroll
        for (int m = 0; m < 8; m++) {
            int row = wrp * 8 + m;
            int r = row >> 5, ic = row & 31;
            int ih = (r == 0) ? ih_a : ih_b;
            bool rowok = (ih >= 0 && ih < 128);
            const float* src = g_d2o + ((n * 64 + cc * 32 + ic) * 128 + ih) * 128;
            float* dst = s_in + row * 130;
#pragma unroll
            for (int k = 0; k < 5; k++) {
                int c = lane + 32 * k;
                if (c < 130) {
                    int iw = c - 1;
                    dst[c] = (rowok && iw >= 0 && iw < 128) ? src[iw] : 0.f;
                }
            }
        }
        __syncthreads();
#pragma unroll 4
        for (int ic = 0; ic < 32; ic++) {
#pragma unroll
            for (int r = 0; r < 2; r++) {
#pragma unroll
                for (int m = 0; m < 2; m++) {
                    float v = s_in[r * 4160 + ic * 130 + iw_a - m + 1];
                    acc = fmaf(v, s_w[((cc * 32 + ic) << 3) + r * 4 + kw_a + 2 * m], acc);
                }
            }
        }
    }
    xh[n * 65536 + oh * 256 + ow] = __fadd_rn(acc, bb[0]);
}

// ---------------------------------------------------------------------------
extern "C" void kernel_launch(void* const* d_in, const int* in_sizes, int n_in,
                              void* d_out, int out_size) {
    const float* x   = (const float*)d_in[0];
    const float* e1w = (const float*)d_in[1];
    const float* e1b = (const float*)d_in[2];
    const float* e2w = (const float*)d_in[3];
    const float* e2b = (const float*)d_in[4];
    const float* e3w = (const float*)d_in[5];
    const float* e3b = (const float*)d_in[6];
    const float* emb = (const float*)d_in[7];
    const float* d1w = (const float*)d_in[8];
    const float* d1b = (const float*)d_in[9];
    const float* d2w = (const float*)d_in[10];
    const float* d2b = (const float*)d_in[11];
    const float* d3w = (const float*)d_in[12];
    const float* d3b = (const float*)d_in[13];

    float* out = (float*)d_out;
    float* xh = out;
    float* ze = out + 4194304;
    float* zq = out + 4194304 + 16777216;

    static bool attr_done = false;
    if (!attr_done) {
        cudaFuncSetAttribute(k_e2, cudaFuncAttributeMaxDynamicSharedMemorySize, 95232);
        cudaFuncSetAttribute(k_e3, cudaFuncAttributeMaxDynamicSharedMemorySize, 76800);
        cudaFuncSetAttribute(k_d1, cudaFuncAttributeMaxDynamicSharedMemorySize, 110592);
        cudaFuncSetAttribute(k_vq, cudaFuncAttributeMaxDynamicSharedMemorySize, 52416);
        attr_done = true;
    }

    k_en<<<2, 256>>>(emb);
    k_e1<<<dim3(128, 64), 128>>>(x, e1w, e1b);
    k_e2<<<dim3(32, 64), 256, 95232>>>(e2w, e2b);
    k_e3<<<dim3(32, 64), 256, 76800>>>(e3w, e3b, ze);
    k_vq<<<dim3(32, 64), 256, 52416>>>(ze, emb, zq);
    k_d1<<<dim3(16, 64), 256, 110592>>>(ze, zq, d1w, d1b);
    k_d2<<<dim3(128, 64), 256>>>(d2w, d2b);
    k_d3<<<dim3(256, 64), 256>>>(d3w, d3b, xh);
}

// round 12
// speedup vs baseline: 1.0131x; 1.0131x over previous
#include <cuda_runtime.h>

// ---------------------------------------------------------------------------
// VQ-VAE forward, fp32, Eigen-chain-order-exact encoder/VQ, f32x2-packed FMA.
// Round 11: R9 base (best). Weight/codebook staging software-pipelined:
// next phase's slice prefetched into registers during compute (LDG off the
// post-barrier critical path). Numerics bit-identical to R9.
// ---------------------------------------------------------------------------

typedef unsigned long long u64;

__device__ float g_h1[64 * 32 * 128 * 128];
__device__ float g_h2[64 * 64 * 64 * 64];
__device__ float g_d1o[64 * 32 * 64 * 64];
__device__ float g_d2o[64 * 64 * 128 * 128];
__device__ float g_en[512];
__device__ float g_embT[64 * 512];   // [c][code]

__device__ __forceinline__ u64 pk2(float x, float y) {
    u64 r; asm("mov.b64 %0, {%1, %2};" : "=l"(r) : "f"(x), "f"(y)); return r;
}
__device__ __forceinline__ u64 f2fma(u64 a, u64 b, u64 c) {
    u64 d; asm("fma.rn.f32x2 %0, %1, %2, %3;" : "=l"(d) : "l"(a), "l"(b), "l"(c)); return d;
}
__device__ __forceinline__ float2 upk(u64 v) {
    float2 f; asm("mov.b64 {%0, %1}, %2;" : "=f"(f.x), "=f"(f.y) : "l"(v)); return f;
}

// --------------- codebook norms + transpose --------------------------------
__global__ void k_en(const float* __restrict__ emb) {
    int k = blockIdx.x * blockDim.x + threadIdx.x;
    if (k < 512) {
        float s = 0.f;
        for (int c = 0; c < 64; c++) {
            float v = emb[k * 64 + c];
            s = __fadd_rn(s, __fmul_rn(v, v));
            g_embT[c * 512 + k] = v;
        }
        g_en[k] = s;
    }
}

// ------------------------- e1 (verbatim R9) --------------------------------
__global__ __launch_bounds__(128) void k_e1(const float* __restrict__ x,
                                            const float* __restrict__ w,
                                            const float* __restrict__ b) {
    __shared__ float s_in[4 * 258];
    __shared__ float s_w[512];
    const int oh = blockIdx.x, n = blockIdx.y, t = threadIdx.x;
    const int lane = t & 31, wrp = t >> 5;
    {
        int r = wrp;
        int ih = 2 * oh - 1 + r;
        bool rowok = (ih >= 0 && ih < 256);
        const float* src = x + n * 65536 + ih * 256;
        float* dst = s_in + r * 258;
#pragma unroll
        for (int k = 0; k < 9; k++) {
            int c = lane + 32 * k;
            if (c < 258) {
                int iw = c - 1;
                dst[c] = (rowok && iw >= 0 && iw < 256) ? src[iw] : 0.f;
            }
        }
    }
    for (int i = t; i < 512; i += 128) s_w[i] = w[i];
    __syncthreads();
    float acc[32];
#pragma unroll
    for (int o = 0; o < 32; o++) acc[o] = 0.f;
    const int ow = t;
#pragma unroll
    for (int k = 0; k < 16; k++) {
        float v = s_in[(k >> 2) * 258 + 2 * ow + (k & 3)];
#pragma unroll
        for (int o = 0; o < 32; o++) acc[o] = fmaf(v, s_w[o * 16 + k], acc[o]);
    }
    for (int o = 0; o < 32; o++) {
        float r = __fadd_rn(acc[o], b[o]);
        g_h1[((n * 32 + o) * 128 + oh) * 128 + ow] = r > 0.f ? r : 0.f;
    }
}

// ------------------------- e2: 32->64, k4 s2 p1, relu ----------------------
// R9 layout + prefetched weight pipeline (16 phases, 8 w/thread).
__global__ __launch_bounds__(256) void k_e2(const float* __restrict__ w,
                                            const float* __restrict__ b) {
    extern __shared__ float sm[];
    float* s_in = sm;            // 32*10*68 = 21760
    float* s_w  = sm + 21760;    // per (kh,kw): [ic32][oc64] = 2048
    const int bx = blockIdx.x, n = blockIdx.y, t = threadIdx.x;
    const int ow0 = (bx & 1) * 32, oh0 = (bx >> 1) * 4;
    const int tow = t & 7, toh = (t >> 3) & 3, tog = t >> 5;
    const int lane = t & 31, wrp = t >> 5;
#pragma unroll 1
    for (int m = 0; m < 40; m++) {
        int row = wrp * 40 + m;
        int r = row >> 5, ic = row & 31;
        int ih = 2 * oh0 - 1 + r;
        bool rowok = (ih >= 0 && ih < 128);
        const float* src = g_h1 + ((n * 32 + ic) * 128 + ih) * 128;
        float* dst = s_in + ic * 680 + r * 68;
#pragma unroll
        for (int k = 0; k < 3; k++) {
            int c = lane + 32 * k;
            if (c < 66) {
                int iw = 2 * ow0 - 1 + c;
                dst[(c & 1) * 34 + (c >> 1)] =
                    (rowok && iw >= 0 && iw < 128) ? src[iw] : 0.f;
            }
        }
    }
    u64 acc[4][4];
#pragma unroll
    for (int i = 0; i < 4; i++)
#pragma unroll
        for (int j = 0; j < 4; j++) acc[i][j] = 0ull;
    float wreg[8];
#pragma unroll
    for (int k = 0; k < 8; k++) {
        int i = t + 256 * k;
        wreg[k] = w[(((i & 63) * 32 + (i >> 6)) << 4)];       // phase 0
    }
#pragma unroll 1
    for (int ph = 0; ph < 16; ph++) {
        const int kh = ph >> 2, kw = ph & 3;
        __syncthreads();
#pragma unroll
        for (int k = 0; k < 8; k++) s_w[t + 256 * k] = wreg[k];
        if (ph < 15) {
#pragma unroll
            for (int k = 0; k < 8; k++) {
                int i = t + 256 * k;
                wreg[k] = w[(((i & 63) * 32 + (i >> 6)) << 4) + ph + 1];
            }
        }
        __syncthreads();
        const float* pin = s_in + (2 * toh + kh) * 68
                                + (kw & 1) * 34 + (kw >> 1) + tow;
        const float* pwb = s_w + (tog << 3);
#pragma unroll 4
        for (int ic = 0; ic < 32; ic++) {
            const float* pw = pwb + (ic << 6);
            ulonglong2 wa = *(const ulonglong2*)(pw);
            ulonglong2 wb = *(const ulonglong2*)(pw + 4);
            const float* q = pin + ic * 680;
#pragma unroll
            for (int i = 0; i < 4; i++) {
                float v = q[8 * i];
                u64 vv = pk2(v, v);
                acc[i][0] = f2fma(vv, wa.x, acc[i][0]);
                acc[i][1] = f2fma(vv, wa.y, acc[i][1]);
                acc[i][2] = f2fma(vv, wb.x, acc[i][2]);
                acc[i][3] = f2fma(vv, wb.y, acc[i][3]);
            }
        }
    }
    const int oh = oh0 + toh;
#pragma unroll
    for (int i = 0; i < 4; i++) {
        int ow = ow0 + tow + 8 * i;
#pragma unroll
        for (int j = 0; j < 4; j++) {
            float2 f = upk(acc[i][j]);
            int oc0 = tog * 8 + 2 * j;
            float r0 = __fadd_rn(f.x, b[oc0]);
            float r1 = __fadd_rn(f.y, b[oc0 + 1]);
            g_h2[((n * 64 + oc0) * 64 + oh) * 64 + ow]     = r0 > 0.f ? r0 : 0.f;
            g_h2[((n * 64 + oc0 + 1) * 64 + oh) * 64 + ow] = r1 > 0.f ? r1 : 0.f;
        }
    }
}

// ------------------------- e3: 64->64, k3 s1 p1, relu ----------------------
// R9 layout (8ow x 8oc, 32ow x 8oh block) + prefetched weight pipeline.
__global__ __launch_bounds__(256) void k_e3(const float* __restrict__ w,
                                            const float* __restrict__ b,
                                            float* __restrict__ ze) {
    extern __shared__ float sm[];
    float* s_in = sm;            // 64*360 = 23040
    float* s_w  = sm + 23040;    // per (kh,kw): [ic64][oc64] = 4096
    const int bx = blockIdx.x, n = blockIdx.y, t = threadIdx.x;
    const int ow0 = (bx & 1) * 32, oh0 = (bx >> 1) * 8;
    const int tow = t & 3, toh = (t >> 2) & 7, tog = t >> 5;
    const int lane = t & 31, wrp = t >> 5;
#pragma unroll 1
    for (int m = 0; m < 80; m++) {
        int row = wrp * 80 + m;
        int r = row >> 6, ic = row & 63;
        int ih = oh0 - 1 + r;
        bool rowok = (ih >= 0 && ih < 64);
        const float* src = g_h2 + ((n * 64 + ic) * 64 + ih) * 64;
        float* dst = s_in + ic * 360 + r * 36;
        {
            int c = lane;
            int iw = ow0 + c - 1;
            dst[c] = (rowok && iw >= 0 && iw < 64) ? src[iw] : 0.f;
        }
        if (lane < 2) {
            int c = 32 + lane;
            int iw = ow0 + c - 1;
            dst[c] = (rowok && iw >= 0 && iw < 64) ? src[iw] : 0.f;
        }
    }
    u64 acc[8][4];
#pragma unroll
    for (int i = 0; i < 8; i++)
#pragma unroll
        for (int j = 0; j < 4; j++) acc[i][j] = 0ull;
    float wreg[16];
#pragma unroll
    for (int k = 0; k < 16; k++) {
        int i = t + 256 * k;
        wreg[k] = w[((i & 63) * 64 + (i >> 6)) * 9];          // phase 0
    }
#pragma unroll 1
    for (int ph = 0; ph < 9; ph++) {
        const int kh = ph / 3, kw = ph - 3 * kh;
        __syncthreads();
#pragma unroll
        for (int k = 0; k < 16; k++) s_w[t + 256 * k] = wreg[k];
        if (ph < 8) {
#pragma unroll
            for (int k = 0; k < 16; k++) {
                int i = t + 256 * k;
                wreg[k] = w[((i & 63) * 64 + (i >> 6)) * 9 + ph + 1];
            }
        }
        __syncthreads();
        const float* pin = s_in + (toh + kh) * 36 + tow + kw;
        const float* pwb = s_w + (tog << 3);
#pragma unroll 2
        for (int ic = 0; ic < 64; ic++) {
            const float* pw = pwb + (ic << 6);
            ulonglong2 wa = *(const ulonglong2*)(pw);
            ulonglong2 wb = *(const ulonglong2*)(pw + 4);
            const float* q = pin + ic * 360;
#pragma unroll
            for (int i = 0; i < 8; i++) {
                float v = q[4 * i];
                u64 vv = pk2(v, v);
                acc[i][0] = f2fma(vv, wa.x, acc[i][0]);
                acc[i][1] = f2fma(vv, wa.y, acc[i][1]);
                acc[i][2] = f2fma(vv, wb.x, acc[i][2]);
                acc[i][3] = f2fma(vv, wb.y, acc[i][3]);
            }
        }
    }
    const int oh = oh0 + toh;
#pragma unroll
    for (int i = 0; i < 8; i++) {
        int ow = ow0 + tow + 4 * i;
#pragma unroll
        for (int j = 0; j < 4; j++) {
            float2 f = upk(acc[i][j]);
            int oc0 = tog * 8 + 2 * j;
            float r0 = __fadd_rn(f.x, b[oc0]);
            float r1 = __fadd_rn(f.y, b[oc0 + 1]);
            ze[((n * 64 + oc0) * 64 + oh) * 64 + ow]     = r0 > 0.f ? r0 : 0.f;
            ze[((n * 64 + oc0 + 1) * 64 + oh) * 64 + ow] = r1 > 0.f ? r1 : 0.f;
        }
    }
}

// ------------------------- VQ (R9 layout + prefetched codebook) ------------
__global__ __launch_bounds__(256) void k_vq(const float* __restrict__ ze,
                                            const float* __restrict__ emb,
                                            float* __restrict__ zq) {
    extern __shared__ float sm[];
    float* s_z  = sm;            // [hh4 stride 4104] = 16416
    float* s_e  = sm + 16416;    // [c64][code64] = 4096
    float* s_en = sm + 20512;    // 512
    float* s_zz = sm + 21024;    // [hh4 stride 72] = 288
    float* s_bv = sm + 21312;    // 2048
    int*   s_bi = (int*)(sm + 23360);   // 2048
    int*   s_idx = (int*)(sm + 25408);  // 256
    const int h0 = blockIdx.x * 4, n = blockIdx.y, t = threadIdx.x;
    const int tpos = t & 7, th = (t >> 3) & 3, kg = t >> 5;
    for (int i = t; i < 16384; i += 256) {
        int c = i >> 8, hh = (i >> 6) & 3, pos = i & 63;
        s_z[hh * 4104 + c * 64 + pos] =
            ze[n * 262144 + c * 4096 + (h0 + hh) * 64 + pos];
    }
    for (int i = t; i < 512; i += 256) s_en[i] = g_en[i];
    __syncthreads();
    {
        int hh = t >> 6, pp = t & 63;
        float a = 0.f;
        for (int c = 0; c < 64; c++) {
            float v = s_z[hh * 4104 + c * 64 + pp];
            a = __fadd_rn(a, __fmul_rn(v, v));
        }
        s_zz[hh * 72 + pp] = a;
    }
    float bv[8];
    int bi[8];
#pragma unroll
    for (int i = 0; i < 8; i++) { bv[i] = 3.4e38f; bi[i] = 0; }
    float ereg[16];
#pragma unroll
    for (int k = 0; k < 16; k++) {
        int i = t + 256 * k;
        ereg[k] = g_embT[(i >> 6) * 512 + (i & 63)];          // ch 0
    }
#pragma unroll 1
    for (int ch = 0; ch < 8; ch++) {
        __syncthreads();
#pragma unroll
        for (int k = 0; k < 16; k++) s_e[t + 256 * k] = ereg[k];
        if (ch < 7) {
#pragma unroll
            for (int k = 0; k < 16; k++) {
                int i = t + 256 * k;
                ereg[k] = g_embT[(i >> 6) * 512 + (ch + 1) * 64 + (i & 63)];
            }
        }
        __syncthreads();
        u64 dot[8][4];
#pragma unroll
        for (int i = 0; i < 8; i++)
#pragma unroll
            for (int j = 0; j < 4; j++) dot[i][j] = 0ull;
        const float* pz = s_z + th * 4104 + tpos;
        const float* peb = s_e + kg * 8;
#pragma unroll 2
        for (int c = 0; c < 64; c++) {
            const float* pe = peb + (c << 6);
            ulonglong2 e01 = *(const ulonglong2*)(pe);
            ulonglong2 e23 = *(const ulonglong2*)(pe + 4);
            const float* q = pz + (c << 6);
#pragma unroll
            for (int i = 0; i < 8; i++) {
                float v = q[8 * i];
                u64 vv = pk2(v, v);
                dot[i][0] = f2fma(vv, e01.x, dot[i][0]);
                dot[i][1] = f2fma(vv, e01.y, dot[i][1]);
                dot[i][2] = f2fma(vv, e23.x, dot[i][2]);
                dot[i][3] = f2fma(vv, e23.y, dot[i][3]);
            }
        }
#pragma unroll
        for (int i = 0; i < 8; i++) {
            float zz = s_zz[th * 72 + tpos + 8 * i];
#pragma unroll
            for (int j = 0; j < 4; j++) {
                float2 f = upk(dot[i][j]);
                int code0 = ch * 64 + kg * 8 + 2 * j;
                float d0 = __fadd_rn(__fsub_rn(zz, __fmul_rn(2.0f, f.x)), s_en[code0]);
                float d1 = __fadd_rn(__fsub_rn(zz, __fmul_rn(2.0f, f.y)), s_en[code0 + 1]);
                if (d0 < bv[i]) { bv[i] = d0; bi[i] = code0; }
                if (d1 < bv[i]) { bv[i] = d1; bi[i] = code0 + 1; }
            }
        }
    }
#pragma unroll
    for (int i = 0; i < 8; i++) {
        int pos = tpos + 8 * i;
        s_bv[(kg * 4 + th) * 64 + pos] = bv[i];
        s_bi[(kg * 4 + th) * 64 + pos] = bi[i];
    }
    __syncthreads();
    {
        int hh = t >> 6, pp = t & 63;
        float bb = s_bv[hh * 64 + pp];
        int ii = s_bi[hh * 64 + pp];
        for (int q = 1; q < 8; q++) {
            float v2 = s_bv[(q * 4 + hh) * 64 + pp];
            int i2 = s_bi[(q * 4 + hh) * 64 + pp];
            if (v2 < bb || (v2 == bb && i2 < ii)) { bb = v2; ii = i2; }
        }
        s_idx[hh * 64 + pp] = ii;
    }
    __syncthreads();
    for (int i = t; i < 16384; i += 256) {
        int c = i >> 8, hh = (i >> 6) & 3, wq = i & 63;
        zq[n * 262144 + c * 4096 + (h0 + hh) * 64 + wq] =
            emb[s_idx[hh * 64 + wq] * 64 + c];
    }
}

// --------------- d1 (R9 layout + prefetched weight pipeline) ---------------
__global__ __launch_bounds__(256) void k_d1(const float* __restrict__ ze,
                                            const float* __restrict__ zq,
                                            const float* __restrict__ w,
                                            const float* __restrict__ b) {
    extern __shared__ float sm[];
    float* s_in = sm;            // 64*400 = 25600
    float* s_w  = sm + 25600;    // per (kh,kw): [ic64][oc32] = 2048
    const int bx = blockIdx.x, n = blockIdx.y, t = threadIdx.x;
    const int ow0 = (bx & 1) * 32, oh0 = (bx >> 1) * 8;
    const int tow = t & 7, toh = (t >> 3) & 7, tog = t >> 6;
    const int lane = t & 31, wrp = t >> 5;
#pragma unroll 1
    for (int m = 0; m < 80; m++) {
        int row = wrp * 80 + m;
        int r = row >> 6, ic = row & 63;
        int ih = oh0 - 1 + r;
        bool rowok = (ih >= 0 && ih < 64);
        const float* pz = ze + ((n * 64 + ic) * 64 + ih) * 64;
        const float* pq = zq + ((n * 64 + ic) * 64 + ih) * 64;
        float* dst = s_in + ic * 400 + r * 40;
        {
            int c = lane;
            int iw = ow0 + c - 1;
            float v = 0.f;
            if (rowok && iw >= 0 && iw < 64) {
                float a = pz[iw], q = pq[iw];
                v = __fadd_rn(a, __fsub_rn(q, a));
            }
            dst[c] = v;
        }
        if (lane < 2) {
            int c = 32 + lane;
            int iw = ow0 + c - 1;
            float v = 0.f;
            if (rowok && iw >= 0 && iw < 64) {
                float a = pz[iw], q = pq[iw];
                v = __fadd_rn(a, __fsub_rn(q, a));
            }
            dst[c] = v;
        }
    }
    u64 acc[4][4];
#pragma unroll
    for (int i = 0; i < 4; i++)
#pragma unroll
        for (int j = 0; j < 4; j++) acc[i][j] = 0ull;
    float wreg[8];
#pragma unroll
    for (int k = 0; k < 8; k++) {
        int i = t + 256 * k;
        wreg[k] = w[((i >> 5) * 32 + (i & 31)) * 9 + 8];      // phase 0: 8-0
    }
#pragma unroll 1
    for (int ph = 0; ph < 9; ph++) {
        const int kh = ph / 3, kw = ph - 3 * kh;
        __syncthreads();
#pragma unroll
        for (int k = 0; k < 8; k++) s_w[t + 256 * k] = wreg[k];
        if (ph < 8) {
#pragma unroll
            for (int k = 0; k < 8; k++) {
                int i = t + 256 * k;
                wreg[k] = w[((i >> 5) * 32 + (i & 31)) * 9 + 7 - ph];
            }
        }
        __syncthreads();
        const float* pin = s_in + (toh + kh) * 40 + tow + kw;
        const float* pwb = s_w + (tog << 3);
#pragma unroll 2
        for (int ic = 0; ic < 64; ic++) {
            const float* pw = pwb + (ic << 5);
            ulonglong2 wa = *(const ulonglong2*)(pw);
            ulonglong2 wb = *(const ulonglong2*)(pw + 4);
            const float* q = pin + ic * 400;
#pragma unroll
            for (int i = 0; i < 4; i++) {
                float v = q[8 * i];
                u64 vv = pk2(v, v);
                acc[i][0] = f2fma(vv, wa.x, acc[i][0]);
                acc[i][1] = f2fma(vv, wa.y, acc[i][1]);
                acc[i][2] = f2fma(vv, wb.x, acc[i][2]);
                acc[i][3] = f2fma(vv, wb.y, acc[i][3]);
            }
        }
    }
    const int oh = oh0 + toh;
#pragma unroll
    for (int i = 0; i < 4; i++) {
        int ow = ow0 + tow + 8 * i;
#pragma unroll
        for (int j = 0; j < 4; j++) {
            float2 f = upk(acc[i][j]);
            int oc0 = tog * 8 + 2 * j;
            float r0 = f.x + b[oc0];
            float r1 = f.y + b[oc0 + 1];
            g_d1o[((n * 32 + oc0) * 64 + oh) * 64 + ow]     = r0 > 0.f ? r0 : 0.f;
            g_d1o[((n * 32 + oc0 + 1) * 64 + oh) * 64 + ow] = r1 > 0.f ? r1 : 0.f;
        }
    }
}

// --------------- d2 (verbatim R9) ------------------------------------------
__global__ __launch_bounds__(256) void k_d2(const float* __restrict__ w,
                                            const float* __restrict__ b) {
    __shared__ __align__(16) float s_in[2112];
    __shared__ __align__(16) float s_w[8192];
    const int oh = blockIdx.x, n = blockIdx.y, t = threadIdx.x;
    const int p = t & 1, u = (t >> 1) & 15, tog = t >> 5;
    const int lane = t & 31, wrp = t >> 5;
    const int kh_a = 1 - (oh & 1);
    const int ih_a = (oh + 1 - kh_a) >> 1;
    const int kw_a = 1 - p;
    u64 acc[4][4];
#pragma unroll
    for (int i = 0; i < 4; i++)
#pragma unroll
        for (int j = 0; j < 4; j++) acc[i][j] = 0ull;
#pragma unroll 1
    for (int cc = 0; cc < 2; cc++) {
        __syncthreads();
#pragma unroll
        for (int m = 0; m < 4; m++) {
            int row = wrp * 4 + m;
            int r = row >> 4, ic = row & 15;
            int ih = (r == 0) ? ih_a : ih_a - 1;
            bool rowok = (ih >= 0 && ih < 64);
            const float* src = g_d1o + ((n * 32 + cc * 16 + ic) * 64 + ih) * 64;
            float* dst = s_in + row * 66;
#pragma unroll
            for (int k = 0; k < 3; k++) {
                int c = lane + 32 * k;
                if (c < 66) {
                    int iw = c - 1;
                    dst[c] = (rowok && iw >= 0 && iw < 64) ? src[iw] : 0.f;
                }
            }
        }
        for (int i = t; i < 8192; i += 256) {
            int ic = i >> 9, rem = i & 511;
            int r = rem >> 8, kw = (rem >> 6) & 3, oc = rem & 63;
            s_w[i] = w[(((cc * 16 + ic) * 64 + oc) << 4) + (kh_a + 2 * r) * 4 + kw];
        }
        __syncthreads();
#pragma unroll 2
        for (int ic = 0; ic < 16; ic++) {
#pragma unroll
            for (int r = 0; r < 2; r++) {
#pragma unroll
                for (int m = 0; m < 2; m++) {
                    int kw = kw_a + 2 * m;
                    const ulonglong2* pw = (const ulonglong2*)(s_w + ((ic * 2 + r) * 4 + kw) * 64 + tog * 8);
                    const float* q = s_in + r * 1056 + ic * 66 + u + p - m + 1;
                    ulonglong2 w01 = pw[0], w23 = pw[1];
#pragma unroll
                    for (int i = 0; i < 4; i++) {
                        float v = q[16 * i];
                        u64 vv = pk2(v, v);
                        acc[i][0] = f2fma(vv, w01.x, acc[i][0]);
                        acc[i][1] = f2fma(vv, w01.y, acc[i][1]);
                        acc[i][2] = f2fma(vv, w23.x, acc[i][2]);
                        acc[i][3] = f2fma(vv, w23.y, acc[i][3]);
                    }
                }
            }
        }
    }
#pragma unroll
    for (int i = 0; i < 4; i++) {
        int ow = 2 * (u + 16 * i) + p;
#pragma unroll
        for (int j = 0; j < 4; j++) {
            float2 f = upk(acc[i][j]);
            int oc0 = tog * 8 + 2 * j;
            float r0 = f.x + b[oc0];
            float r1 = f.y + b[oc0 + 1];
            g_d2o[((n * 64 + oc0) * 128 + oh) * 128 + ow]     = r0 > 0.f ? r0 : 0.f;
            g_d2o[((n * 64 + oc0 + 1) * 128 + oh) * 128 + ow] = r1 > 0.f ? r1 : 0.f;
        }
    }
}

// --------------- d3 (verbatim R9) ------------------------------------------
__global__ __launch_bounds__(256) void k_d3(const float* __restrict__ w,
                                            const float* __restrict__ bb,
                                            float* __restrict__ xh) {
    __shared__ float s_in[8320];
    __shared__ float s_w[512];
    const int oh = blockIdx.x, n = blockIdx.y, t = threadIdx.x;
    const int ow = t;
    const int lane = t & 31, wrp = t >> 5;
    const int kh_a = 1 - (oh & 1);
    const int ih_a = (oh + 1 - kh_a) >> 1;
    const int ih_b = ih_a - 1;
    const int kw_a = 1 - (ow & 1);
    const int iw_a = (ow + 1 - kw_a) >> 1;
    for (int i = t; i < 512; i += 256) {
        int ic = i >> 3, r = (i >> 2) & 1, kw = i & 3;
        int kh = kh_a + 2 * r;
        s_w[i] = w[ic * 16 + kh * 4 + kw];
    }
    float acc = 0.f;
#pragma unroll 1
    for (int cc = 0; cc < 2; cc++) {
        __syncthreads();
#pragma unroll
        for (int m = 0; m < 8; m++) {
            int row = wrp * 8 + m;
            int r = row >> 5, ic = row & 31;
            int ih = (r == 0) ? ih_a : ih_b;
            bool rowok = (ih >= 0 && ih < 128);
            const float* src = g_d2o + ((n * 64 + cc * 32 + ic) * 128 + ih) * 128;
            float* dst = s_in + row * 130;
#pragma unroll
            for (int k = 0; k < 5; k++) {
                int c = lane + 32 * k;
                if (c < 130) {
                    int iw = c - 1;
                    dst[c] = (rowok && iw >= 0 && iw < 128) ? src[iw] : 0.f;
                }
            }
        }
        __syncthreads();
#pragma unroll 4
        for (int ic = 0; ic < 32; ic++) {
#pragma unroll
            for (int r = 0; r < 2; r++) {
#pragma unroll
                for (int m = 0; m < 2; m++) {
                    float v = s_in[r * 4160 + ic * 130 + iw_a - m + 1];
                    acc = fmaf(v, s_w[((cc * 32 + ic) << 3) + r * 4 + kw_a + 2 * m], acc);
                }
            }
        }
    }
    xh[n * 65536 + oh * 256 + ow] = __fadd_rn(acc, bb[0]);
}

// ---------------------------------------------------------------------------
extern "C" void kernel_launch(void* const* d_in, const int* in_sizes, int n_in,
                              void* d_out, int out_size) {
    const float* x   = (const float*)d_in[0];
    const float* e1w = (const float*)d_in[1];
    const float* e1b = (const float*)d_in[2];
    const float* e2w = (const float*)d_in[3];
    const float* e2b = (const float*)d_in[4];
    const float* e3w = (const float*)d_in[5];
    const float* e3b = (const float*)d_in[6];
    const float* emb = (const float*)d_in[7];
    const float* d1w = (const float*)d_in[8];
    const float* d1b = (const float*)d_in[9];
    const float* d2w = (const float*)d_in[10];
    const float* d2b = (const float*)d_in[11];
    const float* d3w = (const float*)d_in[12];
    const float* d3b = (const float*)d_in[13];

    float* out = (float*)d_out;
    float* xh = out;
    float* ze = out + 4194304;
    float* zq = out + 4194304 + 16777216;

    static bool attr_done = false;
    if (!attr_done) {
        cudaFuncSetAttribute(k_e2, cudaFuncAttributeMaxDynamicSharedMemorySize, 95232);
        cudaFuncSetAttribute(k_e3, cudaFuncAttributeMaxDynamicSharedMemorySize, 108544);
        cudaFuncSetAttribute(k_d1, cudaFuncAttributeMaxDynamicSharedMemorySize, 110592);
        cudaFuncSetAttribute(k_vq, cudaFuncAttributeMaxDynamicSharedMemorySize, 102656);
        attr_done = true;
    }

    k_en<<<2, 256>>>(emb);
    k_e1<<<dim3(128, 64), 128>>>(x, e1w, e1b);
    k_e2<<<dim3(32, 64), 256, 95232>>>(e2w, e2b);
    k_e3<<<dim3(16, 64), 256, 108544>>>(e3w, e3b, ze);
    k_vq<<<dim3(16, 64), 256, 102656>>>(ze, emb, zq);
    k_d1<<<dim3(16, 64), 256, 110592>>>(ze, zq, d1w, d1b);
    k_d2<<<dim3(128, 64), 256>>>(d2w, d2b);
    k_d3<<<dim3(256, 64), 256>>>(d3w, d3b, xh);
}

// round 13
// speedup vs baseline: 1.0328x; 1.0195x over previous
#include <cuda_runtime.h>

// ---------------------------------------------------------------------------
// VQ-VAE forward, fp32, Eigen-chain-order-exact encoder/VQ, f32x2-packed FMA.
// Round 12: R9 base (best, 3185us). e2 kw-pair weight staging (half the
// barriers); e3/d1 ic-unroll 4. Numerics bit-identical to R9.
// ---------------------------------------------------------------------------

typedef unsigned long long u64;

__device__ float g_h1[64 * 32 * 128 * 128];
__device__ float g_h2[64 * 64 * 64 * 64];
__device__ float g_d1o[64 * 32 * 64 * 64];
__device__ float g_d2o[64 * 64 * 128 * 128];
__device__ float g_en[512];
__device__ float g_embT[64 * 512];   // [c][code]

__device__ __forceinline__ u64 pk2(float x, float y) {
    u64 r; asm("mov.b64 %0, {%1, %2};" : "=l"(r) : "f"(x), "f"(y)); return r;
}
__device__ __forceinline__ u64 f2fma(u64 a, u64 b, u64 c) {
    u64 d; asm("fma.rn.f32x2 %0, %1, %2, %3;" : "=l"(d) : "l"(a), "l"(b), "l"(c)); return d;
}
__device__ __forceinline__ float2 upk(u64 v) {
    float2 f; asm("mov.b64 {%0, %1}, %2;" : "=f"(f.x), "=f"(f.y) : "l"(v)); return f;
}

// --------------- codebook norms + transpose --------------------------------
__global__ void k_en(const float* __restrict__ emb) {
    int k = blockIdx.x * blockDim.x + threadIdx.x;
    if (k < 512) {
        float s = 0.f;
        for (int c = 0; c < 64; c++) {
            float v = emb[k * 64 + c];
            s = __fadd_rn(s, __fmul_rn(v, v));
            g_embT[c * 512 + k] = v;
        }
        g_en[k] = s;
    }
}

// ------------------------- e1 (verbatim R9) --------------------------------
__global__ __launch_bounds__(128) void k_e1(const float* __restrict__ x,
                                            const float* __restrict__ w,
                                            const float* __restrict__ b) {
    __shared__ float s_in[4 * 258];
    __shared__ float s_w[512];
    const int oh = blockIdx.x, n = blockIdx.y, t = threadIdx.x;
    const int lane = t & 31, wrp = t >> 5;
    {
        int r = wrp;
        int ih = 2 * oh - 1 + r;
        bool rowok = (ih >= 0 && ih < 256);
        const float* src = x + n * 65536 + ih * 256;
        float* dst = s_in + r * 258;
#pragma unroll
        for (int k = 0; k < 9; k++) {
            int c = lane + 32 * k;
            if (c < 258) {
                int iw = c - 1;
                dst[c] = (rowok && iw >= 0 && iw < 256) ? src[iw] : 0.f;
            }
        }
    }
    for (int i = t; i < 512; i += 128) s_w[i] = w[i];
    __syncthreads();
    float acc[32];
#pragma unroll
    for (int o = 0; o < 32; o++) acc[o] = 0.f;
    const int ow = t;
#pragma unroll
    for (int k = 0; k < 16; k++) {
        float v = s_in[(k >> 2) * 258 + 2 * ow + (k & 3)];
#pragma unroll
        for (int o = 0; o < 32; o++) acc[o] = fmaf(v, s_w[o * 16 + k], acc[o]);
    }
    for (int o = 0; o < 32; o++) {
        float r = __fadd_rn(acc[o], b[o]);
        g_h1[((n * 32 + o) * 128 + oh) * 128 + ow] = r > 0.f ? r : 0.f;
    }
}

// ------------------------- e2: 32->64, k4 s2 p1, relu ----------------------
// R9 layout; weights staged in kw-PAIRS (8 staging phases instead of 16).
__global__ __launch_bounds__(256) void k_e2(const float* __restrict__ w,
                                            const float* __restrict__ b) {
    extern __shared__ float sm[];
    float* s_in = sm;            // 32*10*68 = 21760
    float* s_w  = sm + 21760;    // 2 slices: [kwm2][ic32][oc64] = 4096
    const int bx = blockIdx.x, n = blockIdx.y, t = threadIdx.x;
    const int ow0 = (bx & 1) * 32, oh0 = (bx >> 1) * 4;
    const int tow = t & 7, toh = (t >> 3) & 3, tog = t >> 5;
    const int lane = t & 31, wrp = t >> 5;
#pragma unroll 1
    for (int m = 0; m < 40; m++) {
        int row = wrp * 40 + m;
        int r = row >> 5, ic = row & 31;
        int ih = 2 * oh0 - 1 + r;
        bool rowok = (ih >= 0 && ih < 128);
        const float* src = g_h1 + ((n * 32 + ic) * 128 + ih) * 128;
        float* dst = s_in + ic * 680 + r * 68;
#pragma unroll
        for (int k = 0; k < 3; k++) {
            int c = lane + 32 * k;
            if (c < 66) {
                int iw = 2 * ow0 - 1 + c;
                dst[(c & 1) * 34 + (c >> 1)] =
                    (rowok && iw >= 0 && iw < 128) ? src[iw] : 0.f;
            }
        }
    }
    u64 acc[4][4];
#pragma unroll
    for (int i = 0; i < 4; i++)
#pragma unroll
        for (int j = 0; j < 4; j++) acc[i][j] = 0ull;
#pragma unroll 1
    for (int kh = 0; kh < 4; kh++) {
#pragma unroll 1
        for (int kwp = 0; kwp < 2; kwp++) {
            __syncthreads();
            for (int i = t; i < 4096; i += 256) {
                int kwm = i >> 11, ic = (i >> 6) & 31, oc = i & 63;
                s_w[i] = w[((oc * 32 + ic) << 4) + (kh << 2) + 2 * kwp + kwm];
            }
            __syncthreads();
#pragma unroll
            for (int kwm = 0; kwm < 2; kwm++) {
                int kw = 2 * kwp + kwm;
                const float* pin = s_in + (2 * toh + kh) * 68
                                        + (kw & 1) * 34 + (kw >> 1) + tow;
                const float* pwb = s_w + (kwm << 11) + (tog << 3);
#pragma unroll 4
                for (int ic = 0; ic < 32; ic++) {
                    const float* pw = pwb + (ic << 6);
                    ulonglong2 wa = *(const ulonglong2*)(pw);
                    ulonglong2 wb = *(const ulonglong2*)(pw + 4);
                    const float* q = pin + ic * 680;
#pragma unroll
                    for (int i = 0; i < 4; i++) {
                        float v = q[8 * i];
                        u64 vv = pk2(v, v);
                        acc[i][0] = f2fma(vv, wa.x, acc[i][0]);
                        acc[i][1] = f2fma(vv, wa.y, acc[i][1]);
                        acc[i][2] = f2fma(vv, wb.x, acc[i][2]);
                        acc[i][3] = f2fma(vv, wb.y, acc[i][3]);
                    }
                }
            }
        }
    }
    const int oh = oh0 + toh;
#pragma unroll
    for (int i = 0; i < 4; i++) {
        int ow = ow0 + tow + 8 * i;
#pragma unroll
        for (int j = 0; j < 4; j++) {
            float2 f = upk(acc[i][j]);
            int oc0 = tog * 8 + 2 * j;
            float r0 = __fadd_rn(f.x, b[oc0]);
            float r1 = __fadd_rn(f.y, b[oc0 + 1]);
            g_h2[((n * 64 + oc0) * 64 + oh) * 64 + ow]     = r0 > 0.f ? r0 : 0.f;
            g_h2[((n * 64 + oc0 + 1) * 64 + oh) * 64 + ow] = r1 > 0.f ? r1 : 0.f;
        }
    }
}

// ------------------------- e3: 64->64, k3 s1 p1, relu (R9 + unroll4) -------
__global__ __launch_bounds__(256) void k_e3(const float* __restrict__ w,
                                            const float* __restrict__ b,
                                            float* __restrict__ ze) {
    extern __shared__ float sm[];
    float* s_in = sm;            // 64*360 = 23040
    float* s_w  = sm + 23040;    // per (kh,kw): [ic64][oc64] = 4096
    const int bx = blockIdx.x, n = blockIdx.y, t = threadIdx.x;
    const int ow0 = (bx & 1) * 32, oh0 = (bx >> 1) * 8;
    const int tow = t & 3, toh = (t >> 2) & 7, tog = t >> 5;
    const int lane = t & 31, wrp = t >> 5;
#pragma unroll 1
    for (int m = 0; m < 80; m++) {
        int row = wrp * 80 + m;
        int r = row >> 6, ic = row & 63;
        int ih = oh0 - 1 + r;
        bool rowok = (ih >= 0 && ih < 64);
        const float* src = g_h2 + ((n * 64 + ic) * 64 + ih) * 64;
        float* dst = s_in + ic * 360 + r * 36;
        {
            int c = lane;
            int iw = ow0 + c - 1;
            dst[c] = (rowok && iw >= 0 && iw < 64) ? src[iw] : 0.f;
        }
        if (lane < 2) {
            int c = 32 + lane;
            int iw = ow0 + c - 1;
            dst[c] = (rowok && iw >= 0 && iw < 64) ? src[iw] : 0.f;
        }
    }
    u64 acc[8][4];
#pragma unroll
    for (int i = 0; i < 8; i++)
#pragma unroll
        for (int j = 0; j < 4; j++) acc[i][j] = 0ull;
#pragma unroll 1
    for (int kh = 0; kh < 3; kh++) {
#pragma unroll 1
        for (int kw = 0; kw < 3; kw++) {
            __syncthreads();
            for (int i = t; i < 4096; i += 256) {
                int ic = i >> 6, oc = i & 63;
                s_w[i] = w[(oc * 64 + ic) * 9 + kh * 3 + kw];
            }
            __syncthreads();
            const float* pin = s_in + (toh + kh) * 36 + tow + kw;
            const float* pwb = s_w + (tog << 3);
#pragma unroll 4
            for (int ic = 0; ic < 64; ic++) {
                const float* pw = pwb + (ic << 6);
                ulonglong2 wa = *(const ulonglong2*)(pw);
                ulonglong2 wb = *(const ulonglong2*)(pw + 4);
                const float* q = pin + ic * 360;
#pragma unroll
                for (int i = 0; i < 8; i++) {
                    float v = q[4 * i];
                    u64 vv = pk2(v, v);
                    acc[i][0] = f2fma(vv, wa.x, acc[i][0]);
                    acc[i][1] = f2fma(vv, wa.y, acc[i][1]);
                    acc[i][2] = f2fma(vv, wb.x, acc[i][2]);
                    acc[i][3] = f2fma(vv, wb.y, acc[i][3]);
                }
            }
        }
    }
    const int oh = oh0 + toh;
#pragma unroll
    for (int i = 0; i < 8; i++) {
        int ow = ow0 + tow + 4 * i;
#pragma unroll
        for (int j = 0; j < 4; j++) {
            float2 f = upk(acc[i][j]);
            int oc0 = tog * 8 + 2 * j;
            float r0 = __fadd_rn(f.x, b[oc0]);
            float r1 = __fadd_rn(f.y, b[oc0 + 1]);
            ze[((n * 64 + oc0) * 64 + oh) * 64 + ow]     = r0 > 0.f ? r0 : 0.f;
            ze[((n * 64 + oc0 + 1) * 64 + oh) * 64 + ow] = r1 > 0.f ? r1 : 0.f;
        }
    }
}

// ------------------------- VQ (verbatim R9) --------------------------------
__global__ __launch_bounds__(256) void k_vq(const float* __restrict__ ze,
                                            const float* __restrict__ emb,
                                            float* __restrict__ zq) {
    extern __shared__ float sm[];
    float* s_z  = sm;            // [hh4 stride 4104] = 16416
    float* s_e  = sm + 16416;    // [c64][code64] = 4096
    float* s_en = sm + 20512;    // 512
    float* s_zz = sm + 21024;    // [hh4 stride 72] = 288
    float* s_bv = sm + 21312;    // 2048
    int*   s_bi = (int*)(sm + 23360);   // 2048
    int*   s_idx = (int*)(sm + 25408);  // 256
    const int h0 = blockIdx.x * 4, n = blockIdx.y, t = threadIdx.x;
    const int tpos = t & 7, th = (t >> 3) & 3, kg = t >> 5;
    for (int i = t; i < 16384; i += 256) {
        int c = i >> 8, hh = (i >> 6) & 3, pos = i & 63;
        s_z[hh * 4104 + c * 64 + pos] =
            ze[n * 262144 + c * 4096 + (h0 + hh) * 64 + pos];
    }
    for (int i = t; i < 512; i += 256) s_en[i] = g_en[i];
    __syncthreads();
    {
        int hh = t >> 6, pp = t & 63;
        float a = 0.f;
        for (int c = 0; c < 64; c++) {
            float v = s_z[hh * 4104 + c * 64 + pp];
            a = __fadd_rn(a, __fmul_rn(v, v));
        }
        s_zz[hh * 72 + pp] = a;
    }
    float bv[8];
    int bi[8];
#pragma unroll
    for (int i = 0; i < 8; i++) { bv[i] = 3.4e38f; bi[i] = 0; }
#pragma unroll 1
    for (int ch = 0; ch < 8; ch++) {
        __syncthreads();
        for (int i = t; i < 4096; i += 256)
            s_e[i] = g_embT[(i >> 6) * 512 + ch * 64 + (i & 63)];
        __syncthreads();
        u64 dot[8][4];
#pragma unroll
        for (int i = 0; i < 8; i++)
#pragma unroll
            for (int j = 0; j < 4; j++) dot[i][j] = 0ull;
        const float* pz = s_z + th * 4104 + tpos;
        const float* peb = s_e + kg * 8;
#pragma unroll 2
        for (int c = 0; c < 64; c++) {
            const float* pe = peb + (c << 6);
            ulonglong2 e01 = *(const ulonglong2*)(pe);
            ulonglong2 e23 = *(const ulonglong2*)(pe + 4);
            const float* q = pz + (c << 6);
#pragma unroll
            for (int i = 0; i < 8; i++) {
                float v = q[8 * i];
                u64 vv = pk2(v, v);
                dot[i][0] = f2fma(vv, e01.x, dot[i][0]);
                dot[i][1] = f2fma(vv, e01.y, dot[i][1]);
                dot[i][2] = f2fma(vv, e23.x, dot[i][2]);
                dot[i][3] = f2fma(vv, e23.y, dot[i][3]);
            }
        }
#pragma unroll
        for (int i = 0; i < 8; i++) {
            float zz = s_zz[th * 72 + tpos + 8 * i];
#pragma unroll
            for (int j = 0; j < 4; j++) {
                float2 f = upk(dot[i][j]);
                int code0 = ch * 64 + kg * 8 + 2 * j;
                float d0 = __fadd_rn(__fsub_rn(zz, __fmul_rn(2.0f, f.x)), s_en[code0]);
                float d1 = __fadd_rn(__fsub_rn(zz, __fmul_rn(2.0f, f.y)), s_en[code0 + 1]);
                if (d0 < bv[i]) { bv[i] = d0; bi[i] = code0; }
                if (d1 < bv[i]) { bv[i] = d1; bi[i] = code0 + 1; }
            }
        }
    }
#pragma unroll
    for (int i = 0; i < 8; i++) {
        int pos = tpos + 8 * i;
        s_bv[(kg * 4 + th) * 64 + pos] = bv[i];
        s_bi[(kg * 4 + th) * 64 + pos] = bi[i];
    }
    __syncthreads();
    {
        int hh = t >> 6, pp = t & 63;
        float bb = s_bv[hh * 64 + pp];
        int ii = s_bi[hh * 64 + pp];
        for (int q = 1; q < 8; q++) {
            float v2 = s_bv[(q * 4 + hh) * 64 + pp];
            int i2 = s_bi[(q * 4 + hh) * 64 + pp];
            if (v2 < bb || (v2 == bb && i2 < ii)) { bb = v2; ii = i2; }
        }
        s_idx[hh * 64 + pp] = ii;
    }
    __syncthreads();
    for (int i = t; i < 16384; i += 256) {
        int c = i >> 8, hh = (i >> 6) & 3, wq = i & 63;
        zq[n * 262144 + c * 4096 + (h0 + hh) * 64 + wq] =
            emb[s_idx[hh * 64 + wq] * 64 + c];
    }
}

// --------------- d1 (R9 + unroll4) -----------------------------------------
__global__ __launch_bounds__(256) void k_d1(const float* __restrict__ ze,
                                            const float* __restrict__ zq,
                                            const float* __restrict__ w,
                                            const float* __restrict__ b) {
    extern __shared__ float sm[];
    float* s_in = sm;            // 64*400 = 25600
    float* s_w  = sm + 25600;    // per (kh,kw): [ic64][oc32] = 2048
    const int bx = blockIdx.x, n = blockIdx.y, t = threadIdx.x;
    const int ow0 = (bx & 1) * 32, oh0 = (bx >> 1) * 8;
    const int tow = t & 7, toh = (t >> 3) & 7, tog = t >> 6;
    const int lane = t & 31, wrp = t >> 5;
#pragma unroll 1
    for (int m = 0; m < 80; m++) {
        int row = wrp * 80 + m;
        int r = row >> 6, ic = row & 63;
        int ih = oh0 - 1 + r;
        bool rowok = (ih >= 0 && ih < 64);
        const float* pz = ze + ((n * 64 + ic) * 64 + ih) * 64;
        const float* pq = zq + ((n * 64 + ic) * 64 + ih) * 64;
        float* dst = s_in + ic * 400 + r * 40;
        {
            int c = lane;
            int iw = ow0 + c - 1;
            float v = 0.f;
            if (rowok && iw >= 0 && iw < 64) {
                float a = pz[iw], q = pq[iw];
                v = __fadd_rn(a, __fsub_rn(q, a));
            }
            dst[c] = v;
        }
        if (lane < 2) {
            int c = 32 + lane;
            int iw = ow0 + c - 1;
            float v = 0.f;
            if (rowok && iw >= 0 && iw < 64) {
                float a = pz[iw], q = pq[iw];
                v = __fadd_rn(a, __fsub_rn(q, a));
            }
            dst[c] = v;
        }
    }
    u64 acc[4][4];
#pragma unroll
    for (int i = 0; i < 4; i++)
#pragma unroll
        for (int j = 0; j < 4; j++) acc[i][j] = 0ull;
#pragma unroll 1
    for (int kh = 0; kh < 3; kh++) {
#pragma unroll 1
        for (int kw = 0; kw < 3; kw++) {
            __syncthreads();
            for (int i = t; i < 2048; i += 256) {
                int ic = i >> 5, oc = i & 31;
                s_w[i] = w[(ic * 32 + oc) * 9 + 8 - kh * 3 - kw];
            }
            __syncthreads();
            const float* pin = s_in + (toh + kh) * 40 + tow + kw;
            const float* pwb = s_w + (tog << 3);
#pragma unroll 4
            for (int ic = 0; ic < 64; ic++) {
                const float* pw = pwb + (ic << 5);
                ulonglong2 wa = *(const ulonglong2*)(pw);
                ulonglong2 wb = *(const ulonglong2*)(pw + 4);
                const float* q = pin + ic * 400;
#pragma unroll
                for (int i = 0; i < 4; i++) {
                    float v = q[8 * i];
                    u64 vv = pk2(v, v);
                    acc[i][0] = f2fma(vv, wa.x, acc[i][0]);
                    acc[i][1] = f2fma(vv, wa.y, acc[i][1]);
                    acc[i][2] = f2fma(vv, wb.x, acc[i][2]);
                    acc[i][3] = f2fma(vv, wb.y, acc[i][3]);
                }
            }
        }
    }
    const int oh = oh0 + toh;
#pragma unroll
    for (int i = 0; i < 4; i++) {
        int ow = ow0 + tow + 8 * i;
#pragma unroll
        for (int j = 0; j < 4; j++) {
            float2 f = upk(acc[i][j]);
            int oc0 = tog * 8 + 2 * j;
            float r0 = f.x + b[oc0];
            float r1 = f.y + b[oc0 + 1];
            g_d1o[((n * 32 + oc0) * 64 + oh) * 64 + ow]     = r0 > 0.f ? r0 : 0.f;
            g_d1o[((n * 32 + oc0 + 1) * 64 + oh) * 64 + ow] = r1 > 0.f ? r1 : 0.f;
        }
    }
}

// --------------- d2 (verbatim R9) ------------------------------------------
__global__ __launch_bounds__(256) void k_d2(const float* __restrict__ w,
                                            const float* __restrict__ b) {
    __shared__ __align__(16) float s_in[2112];
    __shared__ __align__(16) float s_w[8192];
    const int oh = blockIdx.x, n = blockIdx.y, t = threadIdx.x;
    const int p = t & 1, u = (t >> 1) & 15, tog = t >> 5;
    const int lane = t & 31, wrp = t >> 5;
    const int kh_a = 1 - (oh & 1);
    const int ih_a = (oh + 1 - kh_a) >> 1;
    const int kw_a = 1 - p;
    u64 acc[4][4];
#pragma unroll
    for (int i = 0; i < 4; i++)
#pragma unroll
        for (int j = 0; j < 4; j++) acc[i][j] = 0ull;
#pragma unroll 1
    for (int cc = 0; cc < 2; cc++) {
        __syncthreads();
#pragma unroll
        for (int m = 0; m < 4; m++) {
            int row = wrp * 4 + m;
            int r = row >> 4, ic = row & 15;
            int ih = (r == 0) ? ih_a : ih_a - 1;
            bool rowok = (ih >= 0 && ih < 64);
            const float* src = g_d1o + ((n * 32 + cc * 16 + ic) * 64 + ih) * 64;
            float* dst = s_in + row * 66;
#pragma unroll
            for (int k = 0; k < 3; k++) {
                int c = lane + 32 * k;
                if (c < 66) {
                    int iw = c - 1;
                    dst[c] = (rowok && iw >= 0 && iw < 64) ? src[iw] : 0.f;
                }
            }
        }
        for (int i = t; i < 8192; i += 256) {
            int ic = i >> 9, rem = i & 511;
            int r = rem >> 8, kw = (rem >> 6) & 3, oc = rem & 63;
            s_w[i] = w[(((cc * 16 + ic) * 64 + oc) << 4) + (kh_a + 2 * r) * 4 + kw];
        }
        __syncthreads();
#pragma unroll 2
        for (int ic = 0; ic < 16; ic++) {
#pragma unroll
            for (int r = 0; r < 2; r++) {
#pragma unroll
                for (int m = 0; m < 2; m++) {
                    int kw = kw_a + 2 * m;
                    const ulonglong2* pw = (const ulonglong2*)(s_w + ((ic * 2 + r) * 4 + kw) * 64 + tog * 8);
                    const float* q = s_in + r * 1056 + ic * 66 + u + p - m + 1;
                    ulonglong2 w01 = pw[0], w23 = pw[1];
#pragma unroll
                    for (int i = 0; i < 4; i++) {
                        float v = q[16 * i];
                        u64 vv = pk2(v, v);
                        acc[i][0] = f2fma(vv, w01.x, acc[i][0]);
                        acc[i][1] = f2fma(vv, w01.y, acc[i][1]);
                        acc[i][2] = f2fma(vv, w23.x, acc[i][2]);
                        acc[i][3] = f2fma(vv, w23.y, acc[i][3]);
                    }
                }
            }
        }
    }
#pragma unroll
    for (int i = 0; i < 4; i++) {
        int ow = 2 * (u + 16 * i) + p;
#pragma unroll
        for (int j = 0; j < 4; j++) {
            float2 f = upk(acc[i][j]);
            int oc0 = tog * 8 + 2 * j;
            float r0 = f.x + b[oc0];
            float r1 = f.y + b[oc0 + 1];
            g_d2o[((n * 64 + oc0) * 128 + oh) * 128 + ow]     = r0 > 0.f ? r0 : 0.f;
            g_d2o[((n * 64 + oc0 + 1) * 128 + oh) * 128 + ow] = r1 > 0.f ? r1 : 0.f;
        }
    }
}

// --------------- d3 (verbatim R9) ------------------------------------------
__global__ __launch_bounds__(256) void k_d3(const float* __restrict__ w,
                                            const float* __restrict__ bb,
                                            float* __restrict__ xh) {
    __shared__ float s_in[8320];
    __shared__ float s_w[512];
    const int oh = blockIdx.x, n = blockIdx.y, t = threadIdx.x;
    const int ow = t;
    const int lane = t & 31, wrp = t >> 5;
    const int kh_a = 1 - (oh & 1);
    const int ih_a = (oh + 1 - kh_a) >> 1;
    const int ih_b = ih_a - 1;
    const int kw_a = 1 - (ow & 1);
    const int iw_a = (ow + 1 - kw_a) >> 1;
    for (int i = t; i < 512; i += 256) {
        int ic = i >> 3, r = (i >> 2) & 1, kw = i & 3;
        int kh = kh_a + 2 * r;
        s_w[i] = w[ic * 16 + kh * 4 + kw];
    }
    float acc = 0.f;
#pragma unroll 1
    for (int cc = 0; cc < 2; cc++) {
        __syncthreads();
#pragma unroll
        for (int m = 0; m < 8; m++) {
            int row = wrp * 8 + m;
            int r = row >> 5, ic = row & 31;
            int ih = (r == 0) ? ih_a : ih_b;
            bool rowok = (ih >= 0 && ih < 128);
            const float* src = g_d2o + ((n * 64 + cc * 32 + ic) * 128 + ih) * 128;
            float* dst = s_in + row * 130;
#pragma unroll
            for (int k = 0; k < 5; k++) {
                int c = lane + 32 * k;
                if (c < 130) {
                    int iw = c - 1;
                    dst[c] = (rowok && iw >= 0 && iw < 128) ? src[iw] : 0.f;
                }
            }
        }
        __syncthreads();
#pragma unroll 4
        for (int ic = 0; ic < 32; ic++) {
#pragma unroll
            for (int r = 0; r < 2; r++) {
#pragma unroll
                for (int m = 0; m < 2; m++) {
                    float v = s_in[r * 4160 + ic * 130 + iw_a - m + 1];
                    acc = fmaf(v, s_w[((cc * 32 + ic) << 3) + r * 4 + kw_a + 2 * m], acc);
                }
            }
        }
    }
    xh[n * 65536 + oh * 256 + ow] = __fadd_rn(acc, bb[0]);
}

// ---------------------------------------------------------------------------
extern "C" void kernel_launch(void* const* d_in, const int* in_sizes, int n_in,
                              void* d_out, int out_size) {
    const float* x   = (const float*)d_in[0];
    const float* e1w = (const float*)d_in[1];
    const float* e1b = (const float*)d_in[2];
    const float* e2w = (const float*)d_in[3];
    const float* e2b = (const float*)d_in[4];
    const float* e3w = (const float*)d_in[5];
    const float* e3b = (const float*)d_in[6];
    const float* emb = (const float*)d_in[7];
    const float* d1w = (const float*)d_in[8];
    const float* d1b = (const float*)d_in[9];
    const float* d2w = (const float*)d_in[10];
    const float* d2b = (const float*)d_in[11];
    const float* d3w = (const float*)d_in[12];
    const float* d3b = (const float*)d_in[13];

    float* out = (float*)d_out;
    float* xh = out;
    float* ze = out + 4194304;
    float* zq = out + 4194304 + 16777216;

    static bool attr_done = false;
    if (!attr_done) {
        cudaFuncSetAttribute(k_e2, cudaFuncAttributeMaxDynamicSharedMemorySize, 103424);
        cudaFuncSetAttribute(k_e3, cudaFuncAttributeMaxDynamicSharedMemorySize, 108544);
        cudaFuncSetAttribute(k_d1, cudaFuncAttributeMaxDynamicSharedMemorySize, 110592);
        cudaFuncSetAttribute(k_vq, cudaFuncAttributeMaxDynamicSharedMemorySize, 102656);
        attr_done = true;
    }

    k_en<<<2, 256>>>(emb);
    k_e1<<<dim3(128, 64), 128>>>(x, e1w, e1b);
    k_e2<<<dim3(32, 64), 256, 103424>>>(e2w, e2b);
    k_e3<<<dim3(16, 64), 256, 108544>>>(e3w, e3b, ze);
    k_vq<<<dim3(16, 64), 256, 102656>>>(ze, emb, zq);
    k_d1<<<dim3(16, 64), 256, 110592>>>(ze, zq, d1w, d1b);
    k_d2<<<dim3(128, 64), 256>>>(d2w, d2b);
    k_d3<<<dim3(256, 64), 256>>>(d3w, d3b, xh);
}

// round 14
// speedup vs baseline: 1.0679x; 1.0339x over previous
#include <cuda_runtime.h>

// ---------------------------------------------------------------------------
// VQ-VAE forward, fp32, Eigen-chain-order-exact encoder/VQ, f32x2-packed FMA.
// Round 13: R9 base; e3/d1 ic-unroll4 (e3 measured win), d2 ic-unroll4.
// e2/vq/others verbatim R9. Numerics bit-identical.
// ---------------------------------------------------------------------------

typedef unsigned long long u64;

__device__ float g_h1[64 * 32 * 128 * 128];
__device__ float g_h2[64 * 64 * 64 * 64];
__device__ float g_d1o[64 * 32 * 64 * 64];
__device__ float g_d2o[64 * 64 * 128 * 128];
__device__ float g_en[512];
__device__ float g_embT[64 * 512];   // [c][code]

__device__ __forceinline__ u64 pk2(float x, float y) {
    u64 r; asm("mov.b64 %0, {%1, %2};" : "=l"(r) : "f"(x), "f"(y)); return r;
}
__device__ __forceinline__ u64 f2fma(u64 a, u64 b, u64 c) {
    u64 d; asm("fma.rn.f32x2 %0, %1, %2, %3;" : "=l"(d) : "l"(a), "l"(b), "l"(c)); return d;
}
__device__ __forceinline__ float2 upk(u64 v) {
    float2 f; asm("mov.b64 {%0, %1}, %2;" : "=f"(f.x), "=f"(f.y) : "l"(v)); return f;
}

// --------------- codebook norms + transpose --------------------------------
__global__ void k_en(const float* __restrict__ emb) {
    int k = blockIdx.x * blockDim.x + threadIdx.x;
    if (k < 512) {
        float s = 0.f;
        for (int c = 0; c < 64; c++) {
            float v = emb[k * 64 + c];
            s = __fadd_rn(s, __fmul_rn(v, v));
            g_embT[c * 512 + k] = v;
        }
        g_en[k] = s;
    }
}

// ------------------------- e1 (verbatim R9) --------------------------------
__global__ __launch_bounds__(128) void k_e1(const float* __restrict__ x,
                                            const float* __restrict__ w,
                                            const float* __restrict__ b) {
    __shared__ float s_in[4 * 258];
    __shared__ float s_w[512];
    const int oh = blockIdx.x, n = blockIdx.y, t = threadIdx.x;
    const int lane = t & 31, wrp = t >> 5;
    {
        int r = wrp;
        int ih = 2 * oh - 1 + r;
        bool rowok = (ih >= 0 && ih < 256);
        const float* src = x + n * 65536 + ih * 256;
        float* dst = s_in + r * 258;
#pragma unroll
        for (int k = 0; k < 9; k++) {
            int c = lane + 32 * k;
            if (c < 258) {
                int iw = c - 1;
                dst[c] = (rowok && iw >= 0 && iw < 256) ? src[iw] : 0.f;
            }
        }
    }
    for (int i = t; i < 512; i += 128) s_w[i] = w[i];
    __syncthreads();
    float acc[32];
#pragma unroll
    for (int o = 0; o < 32; o++) acc[o] = 0.f;
    const int ow = t;
#pragma unroll
    for (int k = 0; k < 16; k++) {
        float v = s_in[(k >> 2) * 258 + 2 * ow + (k & 3)];
#pragma unroll
        for (int o = 0; o < 32; o++) acc[o] = fmaf(v, s_w[o * 16 + k], acc[o]);
    }
    for (int o = 0; o < 32; o++) {
        float r = __fadd_rn(acc[o], b[o]);
        g_h1[((n * 32 + o) * 128 + oh) * 128 + ow] = r > 0.f ? r : 0.f;
    }
}

// ------------------------- e2 (verbatim R9) --------------------------------
__global__ __launch_bounds__(256) void k_e2(const float* __restrict__ w,
                                            const float* __restrict__ b) {
    extern __shared__ float sm[];
    float* s_in = sm;            // 32*10*68 = 21760
    float* s_w  = sm + 21760;    // per (kh,kw): [ic32][oc64] = 2048
    const int bx = blockIdx.x, n = blockIdx.y, t = threadIdx.x;
    const int ow0 = (bx & 1) * 32, oh0 = (bx >> 1) * 4;
    const int tow = t & 7, toh = (t >> 3) & 3, tog = t >> 5;
    const int lane = t & 31, wrp = t >> 5;
#pragma unroll 1
    for (int m = 0; m < 40; m++) {
        int row = wrp * 40 + m;
        int r = row >> 5, ic = row & 31;
        int ih = 2 * oh0 - 1 + r;
        bool rowok = (ih >= 0 && ih < 128);
        const float* src = g_h1 + ((n * 32 + ic) * 128 + ih) * 128;
        float* dst = s_in + ic * 680 + r * 68;
#pragma unroll
        for (int k = 0; k < 3; k++) {
            int c = lane + 32 * k;
            if (c < 66) {
                int iw = 2 * ow0 - 1 + c;
                dst[(c & 1) * 34 + (c >> 1)] =
                    (rowok && iw >= 0 && iw < 128) ? src[iw] : 0.f;
            }
        }
    }
    u64 acc[4][4];
#pragma unroll
    for (int i = 0; i < 4; i++)
#pragma unroll
        for (int j = 0; j < 4; j++) acc[i][j] = 0ull;
#pragma unroll 1
    for (int kh = 0; kh < 4; kh++) {
#pragma unroll 1
        for (int kw = 0; kw < 4; kw++) {
            __syncthreads();
            for (int i = t; i < 2048; i += 256) {
                int ic = i >> 6, oc = i & 63;
                s_w[i] = w[((oc * 32 + ic) << 4) + (kh << 2) + kw];
            }
            __syncthreads();
            const float* pin = s_in + (2 * toh + kh) * 68
                                    + (kw & 1) * 34 + (kw >> 1) + tow;
            const float* pwb = s_w + (tog << 3);
#pragma unroll 4
            for (int ic = 0; ic < 32; ic++) {
                const float* pw = pwb + (ic << 6);
                ulonglong2 wa = *(const ulonglong2*)(pw);
                ulonglong2 wb = *(const ulonglong2*)(pw + 4);
                const float* q = pin + ic * 680;
#pragma unroll
                for (int i = 0; i < 4; i++) {
                    float v = q[8 * i];
                    u64 vv = pk2(v, v);
                    acc[i][0] = f2fma(vv, wa.x, acc[i][0]);
                    acc[i][1] = f2fma(vv, wa.y, acc[i][1]);
                    acc[i][2] = f2fma(vv, wb.x, acc[i][2]);
                    acc[i][3] = f2fma(vv, wb.y, acc[i][3]);
                }
            }
        }
    }
    const int oh = oh0 + toh;
#pragma unroll
    for (int i = 0; i < 4; i++) {
        int ow = ow0 + tow + 8 * i;
#pragma unroll
        for (int j = 0; j < 4; j++) {
            float2 f = upk(acc[i][j]);
            int oc0 = tog * 8 + 2 * j;
            float r0 = __fadd_rn(f.x, b[oc0]);
            float r1 = __fadd_rn(f.y, b[oc0 + 1]);
            g_h2[((n * 64 + oc0) * 64 + oh) * 64 + ow]     = r0 > 0.f ? r0 : 0.f;
            g_h2[((n * 64 + oc0 + 1) * 64 + oh) * 64 + ow] = r1 > 0.f ? r1 : 0.f;
        }
    }
}

// ------------------------- e3: 64->64, k3 s1 p1, relu (R9 + unroll4) -------
__global__ __launch_bounds__(256) void k_e3(const float* __restrict__ w,
                                            const float* __restrict__ b,
                                            float* __restrict__ ze) {
    extern __shared__ float sm[];
    float* s_in = sm;            // 64*360 = 23040
    float* s_w  = sm + 23040;    // per (kh,kw): [ic64][oc64] = 4096
    const int bx = blockIdx.x, n = blockIdx.y, t = threadIdx.x;
    const int ow0 = (bx & 1) * 32, oh0 = (bx >> 1) * 8;
    const int tow = t & 3, toh = (t >> 2) & 7, tog = t >> 5;
    const int lane = t & 31, wrp = t >> 5;
#pragma unroll 1
    for (int m = 0; m < 80; m++) {
        int row = wrp * 80 + m;
        int r = row >> 6, ic = row & 63;
        int ih = oh0 - 1 + r;
        bool rowok = (ih >= 0 && ih < 64);
        const float* src = g_h2 + ((n * 64 + ic) * 64 + ih) * 64;
        float* dst = s_in + ic * 360 + r * 36;
        {
            int c = lane;
            int iw = ow0 + c - 1;
            dst[c] = (rowok && iw >= 0 && iw < 64) ? src[iw] : 0.f;
        }
        if (lane < 2) {
            int c = 32 + lane;
            int iw = ow0 + c - 1;
            dst[c] = (rowok && iw >= 0 && iw < 64) ? src[iw] : 0.f;
        }
    }
    u64 acc[8][4];
#pragma unroll
    for (int i = 0; i < 8; i++)
#pragma unroll
        for (int j = 0; j < 4; j++) acc[i][j] = 0ull;
#pragma unroll 1
    for (int kh = 0; kh < 3; kh++) {
#pragma unroll 1
        for (int kw = 0; kw < 3; kw++) {
            __syncthreads();
            for (int i = t; i < 4096; i += 256) {
                int ic = i >> 6, oc = i & 63;
                s_w[i] = w[(oc * 64 + ic) * 9 + kh * 3 + kw];
            }
            __syncthreads();
            const float* pin = s_in + (toh + kh) * 36 + tow + kw;
            const float* pwb = s_w + (tog << 3);
#pragma unroll 4
            for (int ic = 0; ic < 64; ic++) {
                const float* pw = pwb + (ic << 6);
                ulonglong2 wa = *(const ulonglong2*)(pw);
                ulonglong2 wb = *(const ulonglong2*)(pw + 4);
                const float* q = pin + ic * 360;
#pragma unroll
                for (int i = 0; i < 8; i++) {
                    float v = q[4 * i];
                    u64 vv = pk2(v, v);
                    acc[i][0] = f2fma(vv, wa.x, acc[i][0]);
                    acc[i][1] = f2fma(vv, wa.y, acc[i][1]);
                    acc[i][2] = f2fma(vv, wb.x, acc[i][2]);
                    acc[i][3] = f2fma(vv, wb.y, acc[i][3]);
                }
            }
        }
    }
    const int oh = oh0 + toh;
#pragma unroll
    for (int i = 0; i < 8; i++) {
        int ow = ow0 + tow + 4 * i;
#pragma unroll
        for (int j = 0; j < 4; j++) {
            float2 f = upk(acc[i][j]);
            int oc0 = tog * 8 + 2 * j;
            float r0 = __fadd_rn(f.x, b[oc0]);
            float r1 = __fadd_rn(f.y, b[oc0 + 1]);
            ze[((n * 64 + oc0) * 64 + oh) * 64 + ow]     = r0 > 0.f ? r0 : 0.f;
            ze[((n * 64 + oc0 + 1) * 64 + oh) * 64 + ow] = r1 > 0.f ? r1 : 0.f;
        }
    }
}

// ------------------------- VQ (verbatim R9) --------------------------------
__global__ __launch_bounds__(256) void k_vq(const float* __restrict__ ze,
                                            const float* __restrict__ emb,
                                            float* __restrict__ zq) {
    extern __shared__ float sm[];
    float* s_z  = sm;            // [hh4 stride 4104] = 16416
    float* s_e  = sm + 16416;    // [c64][code64] = 4096
    float* s_en = sm + 20512;    // 512
    float* s_zz = sm + 21024;    // [hh4 stride 72] = 288
    float* s_bv = sm + 21312;    // 2048
    int*   s_bi = (int*)(sm + 23360);   // 2048
    int*   s_idx = (int*)(sm + 25408);  // 256
    const int h0 = blockIdx.x * 4, n = blockIdx.y, t = threadIdx.x;
    const int tpos = t & 7, th = (t >> 3) & 3, kg = t >> 5;
    for (int i = t; i < 16384; i += 256) {
        int c = i >> 8, hh = (i >> 6) & 3, pos = i & 63;
        s_z[hh * 4104 + c * 64 + pos] =
            ze[n * 262144 + c * 4096 + (h0 + hh) * 64 + pos];
    }
    for (int i = t; i < 512; i += 256) s_en[i] = g_en[i];
    __syncthreads();
    {
        int hh = t >> 6, pp = t & 63;
        float a = 0.f;
        for (int c = 0; c < 64; c++) {
            float v = s_z[hh * 4104 + c * 64 + pp];
            a = __fadd_rn(a, __fmul_rn(v, v));
        }
        s_zz[hh * 72 + pp] = a;
    }
    float bv[8];
    int bi[8];
#pragma unroll
    for (int i = 0; i < 8; i++) { bv[i] = 3.4e38f; bi[i] = 0; }
#pragma unroll 1
    for (int ch = 0; ch < 8; ch++) {
        __syncthreads();
        for (int i = t; i < 4096; i += 256)
            s_e[i] = g_embT[(i >> 6) * 512 + ch * 64 + (i & 63)];
        __syncthreads();
        u64 dot[8][4];
#pragma unroll
        for (int i = 0; i < 8; i++)
#pragma unroll
            for (int j = 0; j < 4; j++) dot[i][j] = 0ull;
        const float* pz = s_z + th * 4104 + tpos;
        const float* peb = s_e + kg * 8;
#pragma unroll 2
        for (int c = 0; c < 64; c++) {
            const float* pe = peb + (c << 6);
            ulonglong2 e01 = *(const ulonglong2*)(pe);
            ulonglong2 e23 = *(const ulonglong2*)(pe + 4);
            const float* q = pz + (c << 6);
#pragma unroll
            for (int i = 0; i < 8; i++) {
                float v = q[8 * i];
                u64 vv = pk2(v, v);
                dot[i][0] = f2fma(vv, e01.x, dot[i][0]);
                dot[i][1] = f2fma(vv, e01.y, dot[i][1]);
                dot[i][2] = f2fma(vv, e23.x, dot[i][2]);
                dot[i][3] = f2fma(vv, e23.y, dot[i][3]);
            }
        }
#pragma unroll
        for (int i = 0; i < 8; i++) {
            float zz = s_zz[th * 72 + tpos + 8 * i];
#pragma unroll
            for (int j = 0; j < 4; j++) {
                float2 f = upk(dot[i][j]);
                int code0 = ch * 64 + kg * 8 + 2 * j;
                float d0 = __fadd_rn(__fsub_rn(zz, __fmul_rn(2.0f, f.x)), s_en[code0]);
                float d1 = __fadd_rn(__fsub_rn(zz, __fmul_rn(2.0f, f.y)), s_en[code0 + 1]);
                if (d0 < bv[i]) { bv[i] = d0; bi[i] = code0; }
                if (d1 < bv[i]) { bv[i] = d1; bi[i] = code0 + 1; }
            }
        }
    }
#pragma unroll
    for (int i = 0; i < 8; i++) {
        int pos = tpos + 8 * i;
        s_bv[(kg * 4 + th) * 64 + pos] = bv[i];
        s_bi[(kg * 4 + th) * 64 + pos] = bi[i];
    }
    __syncthreads();
    {
        int hh = t >> 6, pp = t & 63;
        float bb = s_bv[hh * 64 + pp];
        int ii = s_bi[hh * 64 + pp];
        for (int q = 1; q < 8; q++) {
            float v2 = s_bv[(q * 4 + hh) * 64 + pp];
            int i2 = s_bi[(q * 4 + hh) * 64 + pp];
            if (v2 < bb || (v2 == bb && i2 < ii)) { bb = v2; ii = i2; }
        }
        s_idx[hh * 64 + pp] = ii;
    }
    __syncthreads();
    for (int i = t; i < 16384; i += 256) {
        int c = i >> 8, hh = (i >> 6) & 3, wq = i & 63;
        zq[n * 262144 + c * 4096 + (h0 + hh) * 64 + wq] =
            emb[s_idx[hh * 64 + wq] * 64 + c];
    }
}

// --------------- d1 (R9 + unroll4) -----------------------------------------
__global__ __launch_bounds__(256) void k_d1(const float* __restrict__ ze,
                                            const float* __restrict__ zq,
                                            const float* __restrict__ w,
                                            const float* __restrict__ b) {
    extern __shared__ float sm[];
    float* s_in = sm;            // 64*400 = 25600
    float* s_w  = sm + 25600;    // per (kh,kw): [ic64][oc32] = 2048
    const int bx = blockIdx.x, n = blockIdx.y, t = threadIdx.x;
    const int ow0 = (bx & 1) * 32, oh0 = (bx >> 1) * 8;
    const int tow = t & 7, toh = (t >> 3) & 7, tog = t >> 6;
    const int lane = t & 31, wrp = t >> 5;
#pragma unroll 1
    for (int m = 0; m < 80; m++) {
        int row = wrp * 80 + m;
        int r = row >> 6, ic = row & 63;
        int ih = oh0 - 1 + r;
        bool rowok = (ih >= 0 && ih < 64);
        const float* pz = ze + ((n * 64 + ic) * 64 + ih) * 64;
        const float* pq = zq + ((n * 64 + ic) * 64 + ih) * 64;
        float* dst = s_in + ic * 400 + r * 40;
        {
            int c = lane;
            int iw = ow0 + c - 1;
            float v = 0.f;
            if (rowok && iw >= 0 && iw < 64) {
                float a = pz[iw], q = pq[iw];
                v = __fadd_rn(a, __fsub_rn(q, a));
            }
            dst[c] = v;
        }
        if (lane < 2) {
            int c = 32 + lane;
            int iw = ow0 + c - 1;
            float v = 0.f;
            if (rowok && iw >= 0 && iw < 64) {
                float a = pz[iw], q = pq[iw];
                v = __fadd_rn(a, __fsub_rn(q, a));
            }
            dst[c] = v;
        }
    }
    u64 acc[4][4];
#pragma unroll
    for (int i = 0; i < 4; i++)
#pragma unroll
        for (int j = 0; j < 4; j++) acc[i][j] = 0ull;
#pragma unroll 1
    for (int kh = 0; kh < 3; kh++) {
#pragma unroll 1
        for (int kw = 0; kw < 3; kw++) {
            __syncthreads();
            for (int i = t; i < 2048; i += 256) {
                int ic = i >> 5, oc = i & 31;
                s_w[i] = w[(ic * 32 + oc) * 9 + 8 - kh * 3 - kw];
            }
            __syncthreads();
            const float* pin = s_in + (toh + kh) * 40 + tow + kw;
            const float* pwb = s_w + (tog << 3);
#pragma unroll 4
            for (int ic = 0; ic < 64; ic++) {
                const float* pw = pwb + (ic << 5);
                ulonglong2 wa = *(const ulonglong2*)(pw);
                ulonglong2 wb = *(const ulonglong2*)(pw + 4);
                const float* q = pin + ic * 400;
#pragma unroll
                for (int i = 0; i < 4; i++) {
                    float v = q[8 * i];
                    u64 vv = pk2(v, v);
                    acc[i][0] = f2fma(vv, wa.x, acc[i][0]);
                    acc[i][1] = f2fma(vv, wa.y, acc[i][1]);
                    acc[i][2] = f2fma(vv, wb.x, acc[i][2]);
                    acc[i][3] = f2fma(vv, wb.y, acc[i][3]);
                }
            }
        }
    }
    const int oh = oh0 + toh;
#pragma unroll
    for (int i = 0; i < 4; i++) {
        int ow = ow0 + tow + 8 * i;
#pragma unroll
        for (int j = 0; j < 4; j++) {
            float2 f = upk(acc[i][j]);
            int oc0 = tog * 8 + 2 * j;
            float r0 = f.x + b[oc0];
            float r1 = f.y + b[oc0 + 1];
            g_d1o[((n * 32 + oc0) * 64 + oh) * 64 + ow]     = r0 > 0.f ? r0 : 0.f;
            g_d1o[((n * 32 + oc0 + 1) * 64 + oh) * 64 + ow] = r1 > 0.f ? r1 : 0.f;
        }
    }
}

// --------------- d2 (R9 + ic-unroll4) --------------------------------------
__global__ __launch_bounds__(256) void k_d2(const float* __restrict__ w,
                                            const float* __restrict__ b) {
    __shared__ __align__(16) float s_in[2112];
    __shared__ __align__(16) float s_w[8192];
    const int oh = blockIdx.x, n = blockIdx.y, t = threadIdx.x;
    const int p = t & 1, u = (t >> 1) & 15, tog = t >> 5;
    const int lane = t & 31, wrp = t >> 5;
    const int kh_a = 1 - (oh & 1);
    const int ih_a = (oh + 1 - kh_a) >> 1;
    const int kw_a = 1 - p;
    u64 acc[4][4];
#pragma unroll
    for (int i = 0; i < 4; i++)
#pragma unroll
        for (int j = 0; j < 4; j++) acc[i][j] = 0ull;
#pragma unroll 1
    for (int cc = 0; cc < 2; cc++) {
        __syncthreads();
#pragma unroll
        for (int m = 0; m < 4; m++) {
            int row = wrp * 4 + m;
            int r = row >> 4, ic = row & 15;
            int ih = (r == 0) ? ih_a : ih_a - 1;
            bool rowok = (ih >= 0 && ih < 64);
            const float* src = g_d1o + ((n * 32 + cc * 16 + ic) * 64 + ih) * 64;
            float* dst = s_in + row * 66;
#pragma unroll
            for (int k = 0; k < 3; k++) {
                int c = lane + 32 * k;
                if (c < 66) {
                    int iw = c - 1;
                    dst[c] = (rowok && iw >= 0 && iw < 64) ? src[iw] : 0.f;
                }
            }
        }
        for (int i = t; i < 8192; i += 256) {
            int ic = i >> 9, rem = i & 511;
            int r = rem >> 8, kw = (rem >> 6) & 3, oc = rem & 63;
            s_w[i] = w[(((cc * 16 + ic) * 64 + oc) << 4) + (kh_a + 2 * r) * 4 + kw];
        }
        __syncthreads();
#pragma unroll 4
        for (int ic = 0; ic < 16; ic++) {
#pragma unroll
            for (int r = 0; r < 2; r++) {
#pragma unroll
                for (int m = 0; m < 2; m++) {
                    int kw = kw_a + 2 * m;
                    const ulonglong2* pw = (const ulonglong2*)(s_w + ((ic * 2 + r) * 4 + kw) * 64 + tog * 8);
                    const float* q = s_in + r * 1056 + ic * 66 + u + p - m + 1;
                    ulonglong2 w01 = pw[0], w23 = pw[1];
#pragma unroll
                    for (int i = 0; i < 4; i++) {
                        float v = q[16 * i];
                        u64 vv = pk2(v, v);
                        acc[i][0] = f2fma(vv, w01.x, acc[i][0]);
                        acc[i][1] = f2fma(vv, w01.y, acc[i][1]);
                        acc[i][2] = f2fma(vv, w23.x, acc[i][2]);
                        acc[i][3] = f2fma(vv, w23.y, acc[i][3]);
                    }
                }
            }
        }
    }
#pragma unroll
    for (int i = 0; i < 4; i++) {
        int ow = 2 * (u + 16 * i) + p;
#pragma unroll
        for (int j = 0; j < 4; j++) {
            float2 f = upk(acc[i][j]);
            int oc0 = tog * 8 + 2 * j;
            float r0 = f.x + b[oc0];
            float r1 = f.y + b[oc0 + 1];
            g_d2o[((n * 64 + oc0) * 128 + oh) * 128 + ow]     = r0 > 0.f ? r0 : 0.f;
            g_d2o[((n * 64 + oc0 + 1) * 128 + oh) * 128 + ow] = r1 > 0.f ? r1 : 0.f;
        }
    }
}

// --------------- d3 (verbatim R9) ------------------------------------------
__global__ __launch_bounds__(256) void k_d3(const float* __restrict__ w,
                                            const float* __restrict__ bb,
                                            float* __restrict__ xh) {
    __shared__ float s_in[8320];
    __shared__ float s_w[512];
    const int oh = blockIdx.x, n = blockIdx.y, t = threadIdx.x;
    const int ow = t;
    const int lane = t & 31, wrp = t >> 5;
    const int kh_a = 1 - (oh & 1);
    const int ih_a = (oh + 1 - kh_a) >> 1;
    const int ih_b = ih_a - 1;
    const int kw_a = 1 - (ow & 1);
    const int iw_a = (ow + 1 - kw_a) >> 1;
    for (int i = t; i < 512; i += 256) {
        int ic = i >> 3, r = (i >> 2) & 1, kw = i & 3;
        int kh = kh_a + 2 * r;
        s_w[i] = w[ic * 16 + kh * 4 + kw];
    }
    float acc = 0.f;
#pragma unroll 1
    for (int cc = 0; cc < 2; cc++) {
        __syncthreads();
#pragma unroll
        for (int m = 0; m < 8; m++) {
            int row = wrp * 8 + m;
            int r = row >> 5, ic = row & 31;
            int ih = (r == 0) ? ih_a : ih_b;
            bool rowok = (ih >= 0 && ih < 128);
            const float* src = g_d2o + ((n * 64 + cc * 32 + ic) * 128 + ih) * 128;
            float* dst = s_in + row * 130;
#pragma unroll
            for (int k = 0; k < 5; k++) {
                int c = lane + 32 * k;
                if (c < 130) {
                    int iw = c - 1;
                    dst[c] = (rowok && iw >= 0 && iw < 128) ? src[iw] : 0.f;
                }
            }
        }
        __syncthreads();
#pragma unroll 4
        for (int ic = 0; ic < 32; ic++) {
#pragma unroll
            for (int r = 0; r < 2; r++) {
#pragma unroll
                for (int m = 0; m < 2; m++) {
                    float v = s_in[r * 4160 + ic * 130 + iw_a - m + 1];
                    acc = fmaf(v, s_w[((cc * 32 + ic) << 3) + r * 4 + kw_a + 2 * m], acc);
                }
            }
        }
    }
    xh[n * 65536 + oh * 256 + ow] = __fadd_rn(acc, bb[0]);
}

// ---------------------------------------------------------------------------
extern "C" void kernel_launch(void* const* d_in, const int* in_sizes, int n_in,
                              void* d_out, int out_size) {
    const float* x   = (const float*)d_in[0];
    const float* e1w = (const float*)d_in[1];
    const float* e1b = (const float*)d_in[2];
    const float* e2w = (const float*)d_in[3];
    const float* e2b = (const float*)d_in[4];
    const float* e3w = (const float*)d_in[5];
    const float* e3b = (const float*)d_in[6];
    const float* emb = (const float*)d_in[7];
    const float* d1w = (const float*)d_in[8];
    const float* d1b = (const float*)d_in[9];
    const float* d2w = (const float*)d_in[10];
    const float* d2b = (const float*)d_in[11];
    const float* d3w = (const float*)d_in[12];
    const float* d3b = (const float*)d_in[13];

    float* out = (float*)d_out;
    float* xh = out;
    float* ze = out + 4194304;
    float* zq = out + 4194304 + 16777216;

    static bool attr_done = false;
    if (!attr_done) {
        cudaFuncSetAttribute(k_e2, cudaFuncAttributeMaxDynamicSharedMemorySize, 95232);
        cudaFuncSetAttribute(k_e3, cudaFuncAttributeMaxDynamicSharedMemorySize, 108544);
        cudaFuncSetAttribute(k_d1, cudaFuncAttributeMaxDynamicSharedMemorySize, 110592);
        cudaFuncSetAttribute(k_vq, cudaFuncAttributeMaxDynamicSharedMemorySize, 102656);
        attr_done = true;
    }

    k_en<<<2, 256>>>(emb);
    k_e1<<<dim3(128, 64), 128>>>(x, e1w, e1b);
    k_e2<<<dim3(32, 64), 256, 95232>>>(e2w, e2b);
    k_e3<<<dim3(16, 64), 256, 108544>>>(e3w, e3b, ze);
    k_vq<<<dim3(16, 64), 256, 102656>>>(ze, emb, zq);
    k_d1<<<dim3(16, 64), 256, 110592>>>(ze, zq, d1w, d1b);
    k_d2<<<dim3(128, 64), 256>>>(d2w, d2b);
    k_d3<<<dim3(256, 64), 256>>>(d3w, d3b, xh);
}

// round 15
// speedup vs baseline: 1.2849x; 1.2032x over previous
#include <cuda_runtime.h>

// ---------------------------------------------------------------------------
// VQ-VAE forward, fp32, Eigen-chain-order-exact encoder/VQ, f32x2-packed FMA.
// Round 14: R13 base (best, 3147us) + weights pre-transposed into staging
// order ([phase][ic][oc]) so per-phase smem staging LDGs are coalesced.
// Numerics bit-identical.
// ---------------------------------------------------------------------------

typedef unsigned long long u64;

__device__ float g_h1[64 * 32 * 128 * 128];
__device__ float g_h2[64 * 64 * 64 * 64];
__device__ float g_d1o[64 * 32 * 64 * 64];
__device__ float g_d2o[64 * 64 * 128 * 128];
__device__ float g_en[512];
__device__ float g_embT[64 * 512];   // [c][code]
__device__ float g_wt2[16 * 32 * 64];   // e2: [ph16][ic32][oc64]
__device__ float g_wt3[9 * 64 * 64];    // e3: [ph9][ic64][oc64]
__device__ float g_wt1[9 * 64 * 32];    // d1: [ph9][ic64][oc32] (flipped)
__device__ float g_wtd2[2 * 2 * 8192];  // d2: [kh_a2][cc2][ic16|r2|kw4|oc64]

__device__ __forceinline__ u64 pk2(float x, float y) {
    u64 r; asm("mov.b64 %0, {%1, %2};" : "=l"(r) : "f"(x), "f"(y)); return r;
}
__device__ __forceinline__ u64 f2fma(u64 a, u64 b, u64 c) {
    u64 d; asm("fma.rn.f32x2 %0, %1, %2, %3;" : "=l"(d) : "l"(a), "l"(b), "l"(c)); return d;
}
__device__ __forceinline__ float2 upk(u64 v) {
    float2 f; asm("mov.b64 {%0, %1}, %2;" : "=f"(f.x), "=f"(f.y) : "l"(v)); return f;
}

// --------------- weight pre-transpose (one tiny launch) --------------------
__global__ void k_wt(const float* __restrict__ e2w, const float* __restrict__ e3w,
                     const float* __restrict__ d1w, const float* __restrict__ d2w) {
    int j = blockIdx.x * 256 + threadIdx.x;
    if (j < 32768) {
        int ph = j >> 11, ic = (j >> 6) & 31, oc = j & 63;
        g_wt2[j] = e2w[((oc * 32 + ic) << 4) + ph];
    } else if (j < 69632) {
        int i = j - 32768;
        int ph = i / 4096, r = i & 4095, ic = r >> 6, oc = r & 63;
        g_wt3[i] = e3w[(oc * 64 + ic) * 9 + ph];
    } else if (j < 88064) {
        int i = j - 69632;
        int ph = i / 2048, r = i & 2047, ic = r >> 5, oc = r & 31;
        g_wt1[i] = d1w[(ic * 32 + oc) * 9 + 8 - ph];
    } else if (j < 120832) {
        int i = j - 88064;
        int q = i & 8191;
        int kha = i >> 14, cc = (i >> 13) & 1;
        int ic = q >> 9, rem = q & 511;
        int r = rem >> 8, kw = (rem >> 6) & 3, oc = rem & 63;
        g_wtd2[i] = d2w[(((cc * 16 + ic) * 64 + oc) << 4) + (kha + 2 * r) * 4 + kw];
    }
}

// --------------- codebook norms + transpose --------------------------------
__global__ void k_en(const float* __restrict__ emb) {
    int k = blockIdx.x * blockDim.x + threadIdx.x;
    if (k < 512) {
        float s = 0.f;
        for (int c = 0; c < 64; c++) {
            float v = emb[k * 64 + c];
            s = __fadd_rn(s, __fmul_rn(v, v));
            g_embT[c * 512 + k] = v;
        }
        g_en[k] = s;
    }
}

// ------------------------- e1 (verbatim R13) -------------------------------
__global__ __launch_bounds__(128) void k_e1(const float* __restrict__ x,
                                            const float* __restrict__ w,
                                            const float* __restrict__ b) {
    __shared__ float s_in[4 * 258];
    __shared__ float s_w[512];
    const int oh = blockIdx.x, n = blockIdx.y, t = threadIdx.x;
    const int lane = t & 31, wrp = t >> 5;
    {
        int r = wrp;
        int ih = 2 * oh - 1 + r;
        bool rowok = (ih >= 0 && ih < 256);
        const float* src = x + n * 65536 + ih * 256;
        float* dst = s_in + r * 258;
#pragma unroll
        for (int k = 0; k < 9; k++) {
            int c = lane + 32 * k;
            if (c < 258) {
                int iw = c - 1;
                dst[c] = (rowok && iw >= 0 && iw < 256) ? src[iw] : 0.f;
            }
        }
    }
    for (int i = t; i < 512; i += 128) s_w[i] = w[i];
    __syncthreads();
    float acc[32];
#pragma unroll
    for (int o = 0; o < 32; o++) acc[o] = 0.f;
    const int ow = t;
#pragma unroll
    for (int k = 0; k < 16; k++) {
        float v = s_in[(k >> 2) * 258 + 2 * ow + (k & 3)];
#pragma unroll
        for (int o = 0; o < 32; o++) acc[o] = fmaf(v, s_w[o * 16 + k], acc[o]);
    }
    for (int o = 0; o < 32; o++) {
        float r = __fadd_rn(acc[o], b[o]);
        g_h1[((n * 32 + o) * 128 + oh) * 128 + ow] = r > 0.f ? r : 0.f;
    }
}

// ------------------------- e2 (R13 + coalesced staging) --------------------
__global__ __launch_bounds__(256) void k_e2(const float* __restrict__ b) {
    extern __shared__ float sm[];
    float* s_in = sm;            // 32*10*68 = 21760
    float* s_w  = sm + 21760;    // per (kh,kw): [ic32][oc64] = 2048
    const int bx = blockIdx.x, n = blockIdx.y, t = threadIdx.x;
    const int ow0 = (bx & 1) * 32, oh0 = (bx >> 1) * 4;
    const int tow = t & 7, toh = (t >> 3) & 3, tog = t >> 5;
    const int lane = t & 31, wrp = t >> 5;
#pragma unroll 1
    for (int m = 0; m < 40; m++) {
        int row = wrp * 40 + m;
        int r = row >> 5, ic = row & 31;
        int ih = 2 * oh0 - 1 + r;
        bool rowok = (ih >= 0 && ih < 128);
        const float* src = g_h1 + ((n * 32 + ic) * 128 + ih) * 128;
        float* dst = s_in + ic * 680 + r * 68;
#pragma unroll
        for (int k = 0; k < 3; k++) {
            int c = lane + 32 * k;
            if (c < 66) {
                int iw = 2 * ow0 - 1 + c;
                dst[(c & 1) * 34 + (c >> 1)] =
                    (rowok && iw >= 0 && iw < 128) ? src[iw] : 0.f;
            }
        }
    }
    u64 acc[4][4];
#pragma unroll
    for (int i = 0; i < 4; i++)
#pragma unroll
        for (int j = 0; j < 4; j++) acc[i][j] = 0ull;
#pragma unroll 1
    for (int kh = 0; kh < 4; kh++) {
#pragma unroll 1
        for (int kw = 0; kw < 4; kw++) {
            __syncthreads();
            {
                const float* wt = g_wt2 + (((kh << 2) + kw) << 11);
                for (int i = t; i < 2048; i += 256) s_w[i] = wt[i];
            }
            __syncthreads();
            const float* pin = s_in + (2 * toh + kh) * 68
                                    + (kw & 1) * 34 + (kw >> 1) + tow;
            const float* pwb = s_w + (tog << 3);
#pragma unroll 4
            for (int ic = 0; ic < 32; ic++) {
                const float* pw = pwb + (ic << 6);
                ulonglong2 wa = *(const ulonglong2*)(pw);
                ulonglong2 wb = *(const ulonglong2*)(pw + 4);
                const float* q = pin + ic * 680;
#pragma unroll
                for (int i = 0; i < 4; i++) {
                    float v = q[8 * i];
                    u64 vv = pk2(v, v);
                    acc[i][0] = f2fma(vv, wa.x, acc[i][0]);
                    acc[i][1] = f2fma(vv, wa.y, acc[i][1]);
                    acc[i][2] = f2fma(vv, wb.x, acc[i][2]);
                    acc[i][3] = f2fma(vv, wb.y, acc[i][3]);
                }
            }
        }
    }
    const int oh = oh0 + toh;
#pragma unroll
    for (int i = 0; i < 4; i++) {
        int ow = ow0 + tow + 8 * i;
#pragma unroll
        for (int j = 0; j < 4; j++) {
            float2 f = upk(acc[i][j]);
            int oc0 = tog * 8 + 2 * j;
            float r0 = __fadd_rn(f.x, b[oc0]);
            float r1 = __fadd_rn(f.y, b[oc0 + 1]);
            g_h2[((n * 64 + oc0) * 64 + oh) * 64 + ow]     = r0 > 0.f ? r0 : 0.f;
            g_h2[((n * 64 + oc0 + 1) * 64 + oh) * 64 + ow] = r1 > 0.f ? r1 : 0.f;
        }
    }
}

// ------------------------- e3 (R13 + coalesced staging) --------------------
__global__ __launch_bounds__(256) void k_e3(const float* __restrict__ b,
                                            float* __restrict__ ze) {
    extern __shared__ float sm[];
    float* s_in = sm;            // 64*360 = 23040
    float* s_w  = sm + 23040;    // per (kh,kw): [ic64][oc64] = 4096
    const int bx = blockIdx.x, n = blockIdx.y, t = threadIdx.x;
    const int ow0 = (bx & 1) * 32, oh0 = (bx >> 1) * 8;
    const int tow = t & 3, toh = (t >> 2) & 7, tog = t >> 5;
    const int lane = t & 31, wrp = t >> 5;
#pragma unroll 1
    for (int m = 0; m < 80; m++) {
        int row = wrp * 80 + m;
        int r = row >> 6, ic = row & 63;
        int ih = oh0 - 1 + r;
        bool rowok = (ih >= 0 && ih < 64);
        const float* src = g_h2 + ((n * 64 + ic) * 64 + ih) * 64;
        float* dst = s_in + ic * 360 + r * 36;
        {
            int c = lane;
            int iw = ow0 + c - 1;
            dst[c] = (rowok && iw >= 0 && iw < 64) ? src[iw] : 0.f;
        }
        if (lane < 2) {
            int c = 32 + lane;
            int iw = ow0 + c - 1;
            dst[c] = (rowok && iw >= 0 && iw < 64) ? src[iw] : 0.f;
        }
    }
    u64 acc[8][4];
#pragma unroll
    for (int i = 0; i < 8; i++)
#pragma unroll
        for (int j = 0; j < 4; j++) acc[i][j] = 0ull;
#pragma unroll 1
    for (int ph = 0; ph < 9; ph++) {
        const int kh = ph / 3, kw = ph - 3 * kh;
        __syncthreads();
        {
            const float* wt = g_wt3 + ph * 4096;
            for (int i = t; i < 4096; i += 256) s_w[i] = wt[i];
        }
        __syncthreads();
        const float* pin = s_in + (toh + kh) * 36 + tow + kw;
        const float* pwb = s_w + (tog << 3);
#pragma unroll 4
        for (int ic = 0; ic < 64; ic++) {
            const float* pw = pwb + (ic << 6);
            ulonglong2 wa = *(const ulonglong2*)(pw);
            ulonglong2 wb = *(const ulonglong2*)(pw + 4);
            const float* q = pin + ic * 360;
#pragma unroll
            for (int i = 0; i < 8; i++) {
                float v = q[4 * i];
                u64 vv = pk2(v, v);
                acc[i][0] = f2fma(vv, wa.x, acc[i][0]);
                acc[i][1] = f2fma(vv, wa.y, acc[i][1]);
                acc[i][2] = f2fma(vv, wb.x, acc[i][2]);
                acc[i][3] = f2fma(vv, wb.y, acc[i][3]);
            }
        }
    }
    const int oh = oh0 + toh;
#pragma unroll
    for (int i = 0; i < 8; i++) {
        int ow = ow0 + tow + 4 * i;
#pragma unroll
        for (int j = 0; j < 4; j++) {
            float2 f = upk(acc[i][j]);
            int oc0 = tog * 8 + 2 * j;
            float r0 = __fadd_rn(f.x, b[oc0]);
            float r1 = __fadd_rn(f.y, b[oc0 + 1]);
            ze[((n * 64 + oc0) * 64 + oh) * 64 + ow]     = r0 > 0.f ? r0 : 0.f;
            ze[((n * 64 + oc0 + 1) * 64 + oh) * 64 + ow] = r1 > 0.f ? r1 : 0.f;
        }
    }
}

// ------------------------- VQ (verbatim R13) -------------------------------
__global__ __launch_bounds__(256) void k_vq(const float* __restrict__ ze,
                                            const float* __restrict__ emb,
                                            float* __restrict__ zq) {
    extern __shared__ float sm[];
    float* s_z  = sm;            // [hh4 stride 4104] = 16416
    float* s_e  = sm + 16416;    // [c64][code64] = 4096
    float* s_en = sm + 20512;    // 512
    float* s_zz = sm + 21024;    // [hh4 stride 72] = 288
    float* s_bv = sm + 21312;    // 2048
    int*   s_bi = (int*)(sm + 23360);   // 2048
    int*   s_idx = (int*)(sm + 25408);  // 256
    const int h0 = blockIdx.x * 4, n = blockIdx.y, t = threadIdx.x;
    const int tpos = t & 7, th = (t >> 3) & 3, kg = t >> 5;
    for (int i = t; i < 16384; i += 256) {
        int c = i >> 8, hh = (i >> 6) & 3, pos = i & 63;
        s_z[hh * 4104 + c * 64 + pos] =
            ze[n * 262144 + c * 4096 + (h0 + hh) * 64 + pos];
    }
    for (int i = t; i < 512; i += 256) s_en[i] = g_en[i];
    __syncthreads();
    {
        int hh = t >> 6, pp = t & 63;
        float a = 0.f;
        for (int c = 0; c < 64; c++) {
            float v = s_z[hh * 4104 + c * 64 + pp];
            a = __fadd_rn(a, __fmul_rn(v, v));
        }
        s_zz[hh * 72 + pp] = a;
    }
    float bv[8];
    int bi[8];
#pragma unroll
    for (int i = 0; i < 8; i++) { bv[i] = 3.4e38f; bi[i] = 0; }
#pragma unroll 1
    for (int ch = 0; ch < 8; ch++) {
        __syncthreads();
        for (int i = t; i < 4096; i += 256)
            s_e[i] = g_embT[(i >> 6) * 512 + ch * 64 + (i & 63)];
        __syncthreads();
        u64 dot[8][4];
#pragma unroll
        for (int i = 0; i < 8; i++)
#pragma unroll
            for (int j = 0; j < 4; j++) dot[i][j] = 0ull;
        const float* pz = s_z + th * 4104 + tpos;
        const float* peb = s_e + kg * 8;
#pragma unroll 2
        for (int c = 0; c < 64; c++) {
            const float* pe = peb + (c << 6);
            ulonglong2 e01 = *(const ulonglong2*)(pe);
            ulonglong2 e23 = *(const ulonglong2*)(pe + 4);
            const float* q = pz + (c << 6);
#pragma unroll
            for (int i = 0; i < 8; i++) {
                float v = q[8 * i];
                u64 vv = pk2(v, v);
                dot[i][0] = f2fma(vv, e01.x, dot[i][0]);
                dot[i][1] = f2fma(vv, e01.y, dot[i][1]);
                dot[i][2] = f2fma(vv, e23.x, dot[i][2]);
                dot[i][3] = f2fma(vv, e23.y, dot[i][3]);
            }
        }
#pragma unroll
        for (int i = 0; i < 8; i++) {
            float zz = s_zz[th * 72 + tpos + 8 * i];
#pragma unroll
            for (int j = 0; j < 4; j++) {
                float2 f = upk(dot[i][j]);
                int code0 = ch * 64 + kg * 8 + 2 * j;
                float d0 = __fadd_rn(__fsub_rn(zz, __fmul_rn(2.0f, f.x)), s_en[code0]);
                float d1 = __fadd_rn(__fsub_rn(zz, __fmul_rn(2.0f, f.y)), s_en[code0 + 1]);
                if (d0 < bv[i]) { bv[i] = d0; bi[i] = code0; }
                if (d1 < bv[i]) { bv[i] = d1; bi[i] = code0 + 1; }
            }
        }
    }
#pragma unroll
    for (int i = 0; i < 8; i++) {
        int pos = tpos + 8 * i;
        s_bv[(kg * 4 + th) * 64 + pos] = bv[i];
        s_bi[(kg * 4 + th) * 64 + pos] = bi[i];
    }
    __syncthreads();
    {
        int hh = t >> 6, pp = t & 63;
        float bb = s_bv[hh * 64 + pp];
        int ii = s_bi[hh * 64 + pp];
        for (int q = 1; q < 8; q++) {
            float v2 = s_bv[(q * 4 + hh) * 64 + pp];
            int i2 = s_bi[(q * 4 + hh) * 64 + pp];
            if (v2 < bb || (v2 == bb && i2 < ii)) { bb = v2; ii = i2; }
        }
        s_idx[hh * 64 + pp] = ii;
    }
    __syncthreads();
    for (int i = t; i < 16384; i += 256) {
        int c = i >> 8, hh = (i >> 6) & 3, wq = i & 63;
        zq[n * 262144 + c * 4096 + (h0 + hh) * 64 + wq] =
            emb[s_idx[hh * 64 + wq] * 64 + c];
    }
}

// --------------- d1 (R13 + coalesced staging) ------------------------------
__global__ __launch_bounds__(256) void k_d1(const float* __restrict__ ze,
                                            const float* __restrict__ zq,
                                            const float* __restrict__ b) {
    extern __shared__ float sm[];
    float* s_in = sm;            // 64*400 = 25600
    float* s_w  = sm + 25600;    // per (kh,kw): [ic64][oc32] = 2048
    const int bx = blockIdx.x, n = blockIdx.y, t = threadIdx.x;
    const int ow0 = (bx & 1) * 32, oh0 = (bx >> 1) * 8;
    const int tow = t & 7, toh = (t >> 3) & 7, tog = t >> 6;
    const int lane = t & 31, wrp = t >> 5;
#pragma unroll 1
    for (int m = 0; m < 80; m++) {
        int row = wrp * 80 + m;
        int r = row >> 6, ic = row & 63;
        int ih = oh0 - 1 + r;
        bool rowok = (ih >= 0 && ih < 64);
        const float* pz = ze + ((n * 64 + ic) * 64 + ih) * 64;
        const float* pq = zq + ((n * 64 + ic) * 64 + ih) * 64;
        float* dst = s_in + ic * 400 + r * 40;
        {
            int c = lane;
            int iw = ow0 + c - 1;
            float v = 0.f;
            if (rowok && iw >= 0 && iw < 64) {
                float a = pz[iw], q = pq[iw];
                v = __fadd_rn(a, __fsub_rn(q, a));
            }
            dst[c] = v;
        }
        if (lane < 2) {
            int c = 32 + lane;
            int iw = ow0 + c - 1;
            float v = 0.f;
            if (rowok && iw >= 0 && iw < 64) {
                float a = pz[iw], q = pq[iw];
                v = __fadd_rn(a, __fsub_rn(q, a));
            }
            dst[c] = v;
        }
    }
    u64 acc[4][4];
#pragma unroll
    for (int i = 0; i < 4; i++)
#pragma unroll
        for (int j = 0; j < 4; j++) acc[i][j] = 0ull;
#pragma unroll 1
    for (int ph = 0; ph < 9; ph++) {
        const int kh = ph / 3, kw = ph - 3 * kh;
        __syncthreads();
        {
            const float* wt = g_wt1 + ph * 2048;
            for (int i = t; i < 2048; i += 256) s_w[i] = wt[i];
        }
        __syncthreads();
        const float* pin = s_in + (toh + kh) * 40 + tow + kw;
        const float* pwb = s_w + (tog << 3);
#pragma unroll 4
        for (int ic = 0; ic < 64; ic++) {
            const float* pw = pwb + (ic << 5);
            ulonglong2 wa = *(const ulonglong2*)(pw);
            ulonglong2 wb = *(const ulonglong2*)(pw + 4);
            const float* q = pin + ic * 400;
#pragma unroll
            for (int i = 0; i < 4; i++) {
                float v = q[8 * i];
                u64 vv = pk2(v, v);
                acc[i][0] = f2fma(vv, wa.x, acc[i][0]);
                acc[i][1] = f2fma(vv, wa.y, acc[i][1]);
                acc[i][2] = f2fma(vv, wb.x, acc[i][2]);
                acc[i][3] = f2fma(vv, wb.y, acc[i][3]);
            }
        }
    }
    const int oh = oh0 + toh;
#pragma unroll
    for (int i = 0; i < 4; i++) {
        int ow = ow0 + tow + 8 * i;
#pragma unroll
        for (int j = 0; j < 4; j++) {
            float2 f = upk(acc[i][j]);
            int oc0 = tog * 8 + 2 * j;
            float r0 = f.x + b[oc0];
            float r1 = f.y + b[oc0 + 1];
            g_d1o[((n * 32 + oc0) * 64 + oh) * 64 + ow]     = r0 > 0.f ? r0 : 0.f;
            g_d1o[((n * 32 + oc0 + 1) * 64 + oh) * 64 + ow] = r1 > 0.f ? r1 : 0.f;
        }
    }
}

// --------------- d2 (R13 + coalesced staging) ------------------------------
__global__ __launch_bounds__(256) void k_d2(const float* __restrict__ b) {
    __shared__ __align__(16) float s_in[2112];
    __shared__ __align__(16) float s_w[8192];
    const int oh = blockIdx.x, n = blockIdx.y, t = threadIdx.x;
    const int p = t & 1, u = (t >> 1) & 15, tog = t >> 5;
    const int lane = t & 31, wrp = t >> 5;
    const int kh_a = 1 - (oh & 1);
    const int ih_a = (oh + 1 - kh_a) >> 1;
    const int kw_a = 1 - p;
    u64 acc[4][4];
#pragma unroll
    for (int i = 0; i < 4; i++)
#pragma unroll
        for (int j = 0; j < 4; j++) acc[i][j] = 0ull;
#pragma unroll 1
    for (int cc = 0; cc < 2; cc++) {
        __syncthreads();
#pragma unroll
        for (int m = 0; m < 4; m++) {
            int row = wrp * 4 + m;
            int r = row >> 4, ic = row & 15;
            int ih = (r == 0) ? ih_a : ih_a - 1;
            bool rowok = (ih >= 0 && ih < 64);
            const float* src = g_d1o + ((n * 32 + cc * 16 + ic) * 64 + ih) * 64;
            float* dst = s_in + row * 66;
#pragma unroll
            for (int k = 0; k < 3; k++) {
                int c = lane + 32 * k;
                if (c < 66) {
                    int iw = c - 1;
                    dst[c] = (rowok && iw >= 0 && iw < 64) ? src[iw] : 0.f;
                }
            }
        }
        {
            const float* wt = g_wtd2 + ((kh_a << 1) + cc) * 8192;
            for (int i = t; i < 8192; i += 256) s_w[i] = wt[i];
        }
        __syncthreads();
#pragma unroll 4
        for (int ic = 0; ic < 16; ic++) {
#pragma unroll
            for (int r = 0; r < 2; r++) {
#pragma unroll
                for (int m = 0; m < 2; m++) {
                    int kw = kw_a + 2 * m;
                    const ulonglong2* pw = (const ulonglong2*)(s_w + ((ic * 2 + r) * 4 + kw) * 64 + tog * 8);
                    const float* q = s_in + r * 1056 + ic * 66 + u + p - m + 1;
                    ulonglong2 w01 = pw[0], w23 = pw[1];
#pragma unroll
                    for (int i = 0; i < 4; i++) {
                        float v = q[16 * i];
                        u64 vv = pk2(v, v);
                        acc[i][0] = f2fma(vv, w01.x, acc[i][0]);
                        acc[i][1] = f2fma(vv, w01.y, acc[i][1]);
                        acc[i][2] = f2fma(vv, w23.x, acc[i][2]);
                        acc[i][3] = f2fma(vv, w23.y, acc[i][3]);
                    }
                }
            }
        }
    }
#pragma unroll
    for (int i = 0; i < 4; i++) {
        int ow = 2 * (u + 16 * i) + p;
#pragma unroll
        for (int j = 0; j < 4; j++) {
            float2 f = upk(acc[i][j]);
            int oc0 = tog * 8 + 2 * j;
            float r0 = f.x + b[oc0];
            float r1 = f.y + b[oc0 + 1];
            g_d2o[((n * 64 + oc0) * 128 + oh) * 128 + ow]     = r0 > 0.f ? r0 : 0.f;
            g_d2o[((n * 64 + oc0 + 1) * 128 + oh) * 128 + ow] = r1 > 0.f ? r1 : 0.f;
        }
    }
}

// --------------- d3 (verbatim R13) -----------------------------------------
__global__ __launch_bounds__(256) void k_d3(const float* __restrict__ w,
                                            const float* __restrict__ bb,
                                            float* __restrict__ xh) {
    __shared__ float s_in[8320];
    __shared__ float s_w[512];
    const int oh = blockIdx.x, n = blockIdx.y, t = threadIdx.x;
    const int ow = t;
    const int lane = t & 31, wrp = t >> 5;
    const int kh_a = 1 - (oh & 1);
    const int ih_a = (oh + 1 - kh_a) >> 1;
    const int ih_b = ih_a - 1;
    const int kw_a = 1 - (ow & 1);
    const int iw_a = (ow + 1 - kw_a) >> 1;
    for (int i = t; i < 512; i += 256) {
        int ic = i >> 3, r = (i >> 2) & 1, kw = i & 3;
        int kh = kh_a + 2 * r;
        s_w[i] = w[ic * 16 + kh * 4 + kw];
    }
    float acc = 0.f;
#pragma unroll 1
    for (int cc = 0; cc < 2; cc++) {
        __syncthreads();
#pragma unroll
        for (int m = 0; m < 8; m++) {
            int row = wrp * 8 + m;
            int r = row >> 5, ic = row & 31;
            int ih = (r == 0) ? ih_a : ih_b;
            bool rowok = (ih >= 0 && ih < 128);
            const float* src = g_d2o + ((n * 64 + cc * 32 + ic) * 128 + ih) * 128;
            float* dst = s_in + row * 130;
#pragma unroll
            for (int k = 0; k < 5; k++) {
                int c = lane + 32 * k;
                if (c < 130) {
                    int iw = c - 1;
                    dst[c] = (rowok && iw >= 0 && iw < 128) ? src[iw] : 0.f;
                }
            }
        }
        __syncthreads();
#pragma unroll 4
        for (int ic = 0; ic < 32; ic++) {
#pragma unroll
            for (int r = 0; r < 2; r++) {
#pragma unroll
                for (int m = 0; m < 2; m++) {
                    float v = s_in[r * 4160 + ic * 130 + iw_a - m + 1];
                    acc = fmaf(v, s_w[((cc * 32 + ic) << 3) + r * 4 + kw_a + 2 * m], acc);
                }
            }
        }
    }
    xh[n * 65536 + oh * 256 + ow] = __fadd_rn(acc, bb[0]);
}

// ---------------------------------------------------------------------------
extern "C" void kernel_launch(void* const* d_in, const int* in_sizes, int n_in,
                              void* d_out, int out_size) {
    const float* x   = (const float*)d_in[0];
    const float* e1w = (const float*)d_in[1];
    const float* e1b = (const float*)d_in[2];
    const float* e2w = (const float*)d_in[3];
    const float* e2b = (const float*)d_in[4];
    const float* e3w = (const float*)d_in[5];
    const float* e3b = (const float*)d_in[6];
    const float* emb = (const float*)d_in[7];
    const float* d1w = (const float*)d_in[8];
    const float* d1b = (const float*)d_in[9];
    const float* d2w = (const float*)d_in[10];
    const float* d2b = (const float*)d_in[11];
    const float* d3w = (const float*)d_in[12];
    const float* d3b = (const float*)d_in[13];

    float* out = (float*)d_out;
    float* xh = out;
    float* ze = out + 4194304;
    float* zq = out + 4194304 + 16777216;

    static bool attr_done = false;
    if (!attr_done) {
        cudaFuncSetAttribute(k_e2, cudaFuncAttributeMaxDynamicSharedMemorySize, 95232);
        cudaFuncSetAttribute(k_e3, cudaFuncAttributeMaxDynamicSharedMemorySize, 108544);
        cudaFuncSetAttribute(k_d1, cudaFuncAttributeMaxDynamicSharedMemorySize, 110592);
        cudaFuncSetAttribute(k_vq, cudaFuncAttributeMaxDynamicSharedMemorySize, 102656);
        attr_done = true;
    }

    k_wt<<<472, 256>>>(e2w, e3w, d1w, d2w);
    k_en<<<2, 256>>>(emb);
    k_e1<<<dim3(128, 64), 128>>>(x, e1w, e1b);
    k_e2<<<dim3(32, 64), 256, 95232>>>(e2b);
    k_e3<<<dim3(16, 64), 256, 108544>>>(e3b, ze);
    k_vq<<<dim3(16, 64), 256, 102656>>>(ze, emb, zq);
    k_d1<<<dim3(16, 64), 256, 110592>>>(ze, zq, d1b);
    k_d2<<<dim3(128, 64), 256>>>(d2b);
    k_d3<<<dim3(256, 64), 256>>>(d3w, d3b, xh);
}